// round 14
// baseline (speedup 1.0000x reference)
#include <cuda_runtime.h>
#include <cuda_bf16.h>
#include <math.h>
#include <stdint.h>

// Problem dims (fixed by the dataset)
#define BB 4
#define LL 4096
#define DD 1024
#define NN 64
#define MM (BB * LL)
#define NCH 512
#define TCH (LL / NCH)    // 8

typedef unsigned int u32;
typedef __nv_bfloat16 bf16;

// ---------------- scratch (device globals: no allocation allowed) ----------------
__device__ bf16 g_WpH[DD * 2 * NN], g_WpL[DD * 2 * NN];   // [1024][128]
__device__ bf16 g_WsH[DD * NN],     g_WsL[DD * NN];       // [1024][64]
__device__ bf16 g_WoH[NN * DD],     g_WoL[NN * DD];       // [64][1024]
__device__ float g_P [MM * NN];                            // dt * Bt * u
__device__ float g_Ct[MM * NN];
__device__ float g_carryT[BB * NN * NCH];                 // transposed partials
__device__ float g_ebias[3 * NN];
__device__ float g_sd[3 * NN];                            // dt | decay | decay^TCH

// ---------------- helpers ----------------
#define SW128(o) ((u32)(o) ^ ((((u32)(o)) >> 3) & 0x70))

__device__ __forceinline__ u32 s2u(const void* p) {
    u32 a;
    asm("{ .reg .u64 t; cvta.to.shared.u64 t, %1; cvt.u32.u64 %0, t; }" : "=r"(a) : "l"(p));
    return a;
}
__device__ __forceinline__ float sp(float v) { return v > 20.f ? v : log1pf(expf(v)); }

#define LDSM4(r, a)                                                                    \
    asm volatile("ldmatrix.sync.aligned.m8n8.x4.shared.b16 {%0,%1,%2,%3}, [%4];"      \
                 : "=r"((r)[0]), "=r"((r)[1]), "=r"((r)[2]), "=r"((r)[3]) : "r"(a))
#define LDSM2T(r, a)                                                                   \
    asm volatile("ldmatrix.sync.aligned.m8n8.x2.trans.shared.b16 {%0,%1}, [%2];"      \
                 : "=r"((r)[0]), "=r"((r)[1]) : "r"(a))
#define MMA(d, a, b)                                                                   \
    asm volatile("mma.sync.aligned.m16n8k16.row.col.f32.bf16.bf16.f32 "               \
                 "{%0,%1,%2,%3}, {%4,%5,%6,%7}, {%8,%9}, {%0,%1,%2,%3};"              \
                 : "+f"((d)[0]), "+f"((d)[1]), "+f"((d)[2]), "+f"((d)[3])             \
                 : "r"((a)[0]), "r"((a)[1]), "r"((a)[2]), "r"((a)[3]),                \
                   "r"((b)[0]), "r"((b)[1]))

#define CPA16(sa, gp)                                                                  \
    asm volatile("cp.async.cg.shared.global [%0], [%1], 16;" :: "r"((u32)(sa)), "l"(gp))
#define CPA_COMMIT() asm volatile("cp.async.commit_group;" ::: "memory")
#define CPA_WAIT1()  asm volatile("cp.async.wait_group 1;" ::: "memory")
#define CPA_WAIT0()  asm volatile("cp.async.wait_group 0;" ::: "memory")

__device__ __forceinline__ void split1(float v, bf16& h, bf16& l) {
    h = __float2bfloat16(v);
    l = __float2bfloat16(v - __bfloat162float(h));
}
__device__ __forceinline__ void split_store8(char* hiP, char* loP, float4 v) {
    bf16 h0, l0, h1, l1, h2, l2, h3, l3;
    split1(v.x, h0, l0); split1(v.y, h1, l1);
    split1(v.z, h2, l2); split1(v.w, h3, l3);
    __nv_bfloat162 hp0 = {h0, h1}, hp1 = {h2, h3};
    __nv_bfloat162 lp0 = {l0, l1}, lp1 = {l2, l3};
    *(uint2*)hiP = make_uint2(*(u32*)&hp0, *(u32*)&hp1);
    *(uint2*)loP = make_uint2(*(u32*)&lp0, *(u32*)&lp1);
}
__device__ __forceinline__ float4 f4fma(float4 acc, float4 a, float4 b) {
    acc.x = fmaf(a.x, b.x, acc.x); acc.y = fmaf(a.y, b.y, acc.y);
    acc.z = fmaf(a.z, b.z, acc.z); acc.w = fmaf(a.w, b.w, acc.w);
    return acc;
}

// ---------------- kernel 0: weight bf16 hi/lo split + ebias + scan consts --------
__global__ void __launch_bounds__(256) prep_kernel(
    const float* __restrict__ Wp, const float* __restrict__ Ws,
    const float* __restrict__ Wo, const float* __restrict__ cb,
    const float* __restrict__ bp, const float* __restrict__ bs,
    const float* __restrict__ A_log, const float* __restrict__ dt_log,
    float* __restrict__ ebias, float* __restrict__ sd)
{
    const int gtid = blockIdx.x * 256 + threadIdx.x;
    const int NT = gridDim.x * 256;

    for (int i = gtid; i < DD * 2 * NN; i += NT) split1(Wp[i], g_WpH[i], g_WpL[i]);
    for (int i = gtid; i < DD * NN;     i += NT) split1(Ws[i], g_WsH[i], g_WsL[i]);
    for (int i = gtid; i < NN * DD;     i += NT) split1(Wo[i], g_WoH[i], g_WoL[i]);

    if (gtid < 2 * NN) {
        float s = bp[gtid];
#pragma unroll 8
        for (int d = 0; d < DD; ++d) s = fmaf(cb[d], Wp[(size_t)d * 2 * NN + gtid], s);
        ebias[gtid] = s;
    } else if (gtid < 3 * NN) {
        ebias[gtid] = bs[gtid - 2 * NN];
    } else if (gtid < 3 * NN + NN) {
        int n = gtid - 3 * NN;
        float dt = sp(dt_log[n]);
        float decay = 1.f - dt * sp(A_log[n]);
        float dp = decay;
#pragma unroll
        for (int i = 0; i < 3; ++i) dp *= dp;      // decay^8 (TCH = 2^3)
        sd[n] = dt;
        sd[NN + n] = decay;
        sd[2 * NN + n] = dp;
    }
}

// ---------------- kernel 1: fused conv + gates + u -> P, Ct, chunk partials ------
#define FX(b)   (0      + (b) * 17408)   // raw x: 67 rows x 256B
#define FBPH(b) (34816  + (b) * 16384)   // Wp hi: 64x128 bf16, 2 panels SW128
#define FBPL(b) (67584  + (b) * 16384)
#define FBSH(b) (100352 + (b) * 8192)    // Ws hi: 64x64 bf16 SW128
#define FBSL(b) (116736 + (b) * 8192)
#define FACH(b) (133120 + (b) * 8192)    // conv split hi
#define FACL(b) (149504 + (b) * 8192)
#define FAXH(b) (165888 + (b) * 8192)    // x split hi
#define FAXL(b) (182272 + (b) * 8192)
#define FUSED_SMEM 198656
#define USTRIDE 66                       // u / P exchange row stride (floats)

__global__ void __launch_bounds__(384, 1) tc_fused(
    const float* __restrict__ x, const float* __restrict__ cw,
    const float* __restrict__ ebias, const float* __restrict__ sd)
{
    extern __shared__ char dsm[];
    const int tid = threadIdx.x;
    const int lane = tid & 31, w = tid >> 5;
    const int m0 = blockIdx.x * 64;
    const bool seqstart = ((m0 & (LL - 1)) == 0);

    const bool is_gate = (w < 8);
    const int mw = is_gate ? ((w >> 2) * 32) : (((w - 8) >> 1) * 32);
    const int nw = is_gate ? ((w & 3) * 32) : (((w - 8) & 1) * 32);

    float acc[2][4][4];
#pragma unroll
    for (int mt = 0; mt < 2; ++mt)
#pragma unroll
        for (int nt = 0; nt < 4; ++nt)
#pragma unroll
            for (int q = 0; q < 4; ++q) acc[mt][nt][q] = 0.f;

    const int arow = lane & 15, acol = (lane >> 4) * 8;
    const int brow = lane & 15;

    const u32 sbase = s2u(dsm);

    auto stage = [&](int kt, int buf) {
        for (int i = tid; i < 67 * 16; i += 384) {
            int rr = i >> 4, ch = i & 15;
            u32 dst = sbase + FX(buf) + rr * 256 + ch * 16;
            if (seqstart && rr < 3) {
                *(uint4*)(dsm + FX(buf) + rr * 256 + ch * 16) = make_uint4(0, 0, 0, 0);
            } else {
                CPA16(dst, x + (size_t)(m0 - 3 + rr) * DD + kt * 64 + ch * 4);
            }
        }
        for (int i = tid; i < 64 * 16; i += 384) {
            int r = i >> 4, ch = i & 15;
            size_t gb = (size_t)(kt * 64 + r) * 256 + ch * 16;
            u32 sw = (u32)(ch >> 3) * 8192 + SW128(r * 128 + (ch & 7) * 16);
            CPA16(sbase + FBPH(buf) + sw, (const char*)g_WpH + gb);
            CPA16(sbase + FBPL(buf) + sw, (const char*)g_WpL + gb);
        }
        for (int i = tid; i < 64 * 8; i += 384) {
            int r = i >> 3, ch = i & 7;
            size_t gb = (size_t)(kt * 64 + r) * 128 + ch * 16;
            u32 sw = SW128(r * 128 + ch * 16);
            CPA16(sbase + FBSH(buf) + sw, (const char*)g_WsH + gb);
            CPA16(sbase + FBSL(buf) + sw, (const char*)g_WsL + gb);
        }
    };

    stage(0, 0);
    CPA_COMMIT();

    for (int kt = 0; kt < DD / 64; ++kt) {
        const int buf = kt & 1;
        if (kt + 1 < DD / 64) {
            stage(kt + 1, buf ^ 1);
            CPA_COMMIT();
            CPA_WAIT1();
        } else {
            CPA_WAIT0();
        }
        __syncthreads();

        // ---- conv + split -> sAc(buf); raw x split -> sAx(buf) ----
        char* sX = dsm + FX(buf);
#pragma unroll
        for (int i = tid; i < 64 * 16; i += 384) {
            int r = i >> 4, ch = i & 15;
            float4 xm3 = *(const float4*)(sX + (r + 0) * 256 + ch * 16);
            float4 xm2 = *(const float4*)(sX + (r + 1) * 256 + ch * 16);
            float4 xm1 = *(const float4*)(sX + (r + 2) * 256 + ch * 16);
            float4 xc  = *(const float4*)(sX + (r + 3) * 256 + ch * 16);
            int dcol = kt * 64 + ch * 4;
            float4 w0 = *(const float4*)(cw + 0 * DD + dcol);
            float4 w1 = *(const float4*)(cw + 1 * DD + dcol);
            float4 w2 = *(const float4*)(cw + 2 * DD + dcol);
            float4 w3 = *(const float4*)(cw + 3 * DD + dcol);
            float4 o = make_float4(0.f, 0.f, 0.f, 0.f);
            o = f4fma(o, w0, xm3); o = f4fma(o, w1, xm2);
            o = f4fma(o, w2, xm1); o = f4fma(o, w3, xc);
            u32 sw = SW128(r * 128 + ch * 8);
            split_store8(dsm + FACH(buf) + sw, dsm + FACL(buf) + sw, o);
            split_store8(dsm + FAXH(buf) + sw, dsm + FAXL(buf) + sw, xc);
        }
        __syncthreads();

        // ---- MMA ----
        const u32 aH = sbase + (is_gate ? FACH(buf) : FAXH(buf));
        const u32 aL = sbase + (is_gate ? FACL(buf) : FAXL(buf));
        const u32 bH = sbase + (is_gate ? FBPH(buf) : FBSH(buf));
        const u32 bL = sbase + (is_gate ? FBPL(buf) : FBSL(buf));
#pragma unroll
        for (int ks = 0; ks < 4; ++ks) {
            u32 ah[2][4], al[2][4], bh[4][2], bl[4][2];
#pragma unroll
            for (int mt = 0; mt < 2; ++mt) {
                u32 off = SW128((mw + mt * 16 + arow) * 128 + (ks * 16 + acol) * 2);
                LDSM4(ah[mt], aH + off);
                LDSM4(al[mt], aL + off);
            }
#pragma unroll
            for (int nt = 0; nt < 4; ++nt) {
                int col = nw + nt * 8;
                u32 off = (u32)(col >> 6) * 8192 +
                          SW128((ks * 16 + brow) * 128 + (col & 63) * 2);
                LDSM2T(bh[nt], bH + off);
                LDSM2T(bl[nt], bL + off);
            }
#pragma unroll
            for (int mt = 0; mt < 2; ++mt)
#pragma unroll
                for (int nt = 0; nt < 4; ++nt) {
                    MMA(acc[mt][nt], ah[mt], bh[nt]);
                    MMA(acc[mt][nt], ah[mt], bl[nt]);
                    MMA(acc[mt][nt], al[mt], bh[nt]);
                }
        }
        // REQUIRED: next iteration's stage() overwrites buffers read above.
        __syncthreads();
    }

    // ---- epilogue: u warps -> smem exchange; gate warps -> P (gmem + smem), Ct --
    float* sU = (float*)dsm;                 // FX(0) region
    float* sP = (float*)(dsm + 17408);       // FX(1) region
    if (!is_gate) {
#pragma unroll
        for (int mt = 0; mt < 2; ++mt)
#pragma unroll
            for (int nt = 0; nt < 4; ++nt) {
                int r = mw + mt * 16 + (lane >> 2);
                int col = nw + nt * 8 + 2 * (lane & 3);
                float b0v = ebias[2 * NN + col], b1v = ebias[2 * NN + col + 1];
                sU[r * USTRIDE + col]           = acc[mt][nt][0] + b0v;
                sU[r * USTRIDE + col + 1]       = acc[mt][nt][1] + b1v;
                sU[(r + 8) * USTRIDE + col]     = acc[mt][nt][2] + b0v;
                sU[(r + 8) * USTRIDE + col + 1] = acc[mt][nt][3] + b1v;
            }
    }
    __syncthreads();
    if (is_gate) {
#pragma unroll
        for (int mt = 0; mt < 2; ++mt)
#pragma unroll
            for (int nt = 0; nt < 4; ++nt) {
                int r = mw + mt * 16 + (lane >> 2);
                int col = nw + nt * 8 + 2 * (lane & 3);
                float b0v = ebias[col], b1v = ebias[col + 1];
                float vx = acc[mt][nt][0] + b0v, vy = acc[mt][nt][1] + b1v;
                float vz = acc[mt][nt][2] + b0v, vw = acc[mt][nt][3] + b1v;
                if (col < 64) {
                    float dt0 = sd[col], dt1 = sd[col + 1];
                    float p0 = dt0 * sp(vx) * sU[r * USTRIDE + col];
                    float p1 = dt1 * sp(vy) * sU[r * USTRIDE + col + 1];
                    float p2 = dt0 * sp(vz) * sU[(r + 8) * USTRIDE + col];
                    float p3 = dt1 * sp(vw) * sU[(r + 8) * USTRIDE + col + 1];
                    *(float2*)&g_P[(size_t)(m0 + r) * NN + col] = make_float2(p0, p1);
                    *(float2*)&g_P[(size_t)(m0 + r + 8) * NN + col] = make_float2(p2, p3);
                    sP[r * USTRIDE + col]           = p0;
                    sP[r * USTRIDE + col + 1]       = p1;
                    sP[(r + 8) * USTRIDE + col]     = p2;
                    sP[(r + 8) * USTRIDE + col + 1] = p3;
                } else {
                    vx = tanhf(vx); vy = tanhf(vy); vz = tanhf(vz); vw = tanhf(vw);
                    *(float2*)&g_Ct[(size_t)(m0 + r) * NN + col - 64] = make_float2(vx, vy);
                    *(float2*)&g_Ct[(size_t)(m0 + r + 8) * NN + col - 64] = make_float2(vz, vw);
                }
            }
    }
    __syncthreads();

    // ---- fused scan_partial: 8 chunks x 64 n over this block's 64 rows ----
    {
        const int bb = m0 >> 12;                       // m0 / LL
        const int ch0 = (m0 & (LL - 1)) >> 3;          // first chunk index
        for (int pair = tid; pair < 8 * 64; pair += 384) {
            int ch_l = pair >> 6, n = pair & 63;
            float decay = sd[NN + n];
            float s = 0.f;
#pragma unroll
            for (int t = 0; t < 8; ++t)
                s = fmaf(decay, s, sP[(ch_l * 8 + t) * USTRIDE + n]);
            g_carryT[((size_t)bb * NN + n) * NCH + ch0 + ch_l] = s;
        }
    }
}

// ---------------- kernel 2: scan_carry (warp-parallel, Kogge-Stone) ----------
__global__ void __launch_bounds__(256) scan_carry(
    const float* __restrict__ sd, float* __restrict__ carryT)
{
    const int wid = threadIdx.x >> 5, lane = threadIdx.x & 31;
    const int row = blockIdx.x * 8 + wid;          // 0..255 = b*NN + n
    const int n = row & (NN - 1);
    const float dp = sd[2 * NN + n];

    float4* p = (float4*)(carryT + (size_t)row * NCH) + lane * 4;
    float4 e0 = p[0], e1 = p[1], e2 = p[2], e3 = p[3];

    float l[16];
    l[0]  = e0.x;
    l[1]  = fmaf(dp, l[0],  e0.y);
    l[2]  = fmaf(dp, l[1],  e0.z);
    l[3]  = fmaf(dp, l[2],  e0.w);
    l[4]  = fmaf(dp, l[3],  e1.x);
    l[5]  = fmaf(dp, l[4],  e1.y);
    l[6]  = fmaf(dp, l[5],  e1.z);
    l[7]  = fmaf(dp, l[6],  e1.w);
    l[8]  = fmaf(dp, l[7],  e2.x);
    l[9]  = fmaf(dp, l[8],  e2.y);
    l[10] = fmaf(dp, l[9],  e2.z);
    l[11] = fmaf(dp, l[10], e2.w);
    l[12] = fmaf(dp, l[11], e3.x);
    l[13] = fmaf(dp, l[12], e3.y);
    l[14] = fmaf(dp, l[13], e3.z);
    l[15] = fmaf(dp, l[14], e3.w);

    const float dp2 = dp * dp, dp4 = dp2 * dp2, dp8 = dp4 * dp4, dp16 = dp8 * dp8;
    float s = l[15], f = dp16;
#pragma unroll
    for (int k = 1; k < 32; k <<= 1) {
        float t = __shfl_up_sync(0xffffffffu, s, k);
        if (lane >= k) s = fmaf(f, t, s);
        f = f * f;
    }
    float prev = __shfl_up_sync(0xffffffffu, s, 1);
    if (lane == 0) prev = 0.f;

    float c[16];
    c[0] = prev;
    float dpj = dp;
#pragma unroll
    for (int j = 1; j < 16; ++j) {
        c[j] = fmaf(dpj, prev, l[j - 1]);
        dpj *= dp;
    }
    p[0] = make_float4(c[0],  c[1],  c[2],  c[3]);
    p[1] = make_float4(c[4],  c[5],  c[6],  c[7]);
    p[2] = make_float4(c[8],  c[9],  c[10], c[11]);
    p[3] = make_float4(c[12], c[13], c[14], c[15]);
}

// ---------------- kernel 3: fused scan_final + output GEMM ----------------
// grid MM/128 blocks, 256 threads (8 warps as 4m x 2n, warp tile 32x64).
// Scans y for 128 rows directly into smem bf16 hi/lo A-tiles, then loops over
// 8 N-chunks of Wo (double-buffered cp.async B staging) and emits out.
#define SOAH 0
#define SOAL 16384
#define SOBH(b) (32768 + (b) * 32768)
#define SOBL(b) (SOBH(b) + 16384)
#define SCANOUT_SMEM 98304

__global__ void __launch_bounds__(256) tc_scan_out(
    const float* __restrict__ P, const float* __restrict__ Ct,
    const float* __restrict__ sd, const float* __restrict__ carryT,
    const float* __restrict__ bo, float* __restrict__ out)
{
    extern __shared__ char dsm[];
    const int tid = threadIdx.x;
    const int lane = tid & 31, w = tid >> 5;
    const int mw = (w >> 1) * 32;      // 4 m-warps
    const int nw = (w & 1) * 64;       // 2 n-warps
    const int m0 = blockIdx.x * 128;
    const int b = m0 >> 12;
    const int l0 = m0 & (LL - 1);

    const u32 sbase = s2u(dsm);
    const int arow = lane & 15, acol = (lane >> 4) * 8;
    const int brow = lane & 15;

    auto stageB = [&](int nc, int buf) {
#pragma unroll
        for (int i = tid; i < 64 * 16; i += 256) {
            int r = i >> 4, ch = i & 15;
            size_t gb = (size_t)r * 2048 + (size_t)nc * 256 + ch * 16;
            u32 sw = (u32)(ch >> 3) * 8192 + SW128(r * 128 + (ch & 7) * 16);
            CPA16(sbase + SOBH(buf) + sw, (const char*)g_WoH + gb);
            CPA16(sbase + SOBL(buf) + sw, (const char*)g_WoL + gb);
        }
    };

    stageB(0, 0);
    CPA_COMMIT();

    // ---- scan phase: 16 chunks x 64 n -> y bf16 hi/lo into smem A-tiles ----
    for (int pair = tid; pair < 16 * 64; pair += 256) {
        int ch_l = pair >> 6, n = pair & 63;
        const float decay = sd[NN + n];
        int chg = (l0 >> 3) + ch_l;
        float s = carryT[((size_t)b * NN + n) * NCH + chg];
        size_t rowbase = (size_t)(m0 + ch_l * 8) * NN + n;
#pragma unroll
        for (int t = 0; t < 8; ++t) {
            size_t idx = rowbase + (size_t)t * NN;
            s = fmaf(decay, s, P[idx]);
            float yv = Ct[idx] * s;
            bf16 h, l;
            split1(yv, h, l);
            u32 sw = SW128((ch_l * 8 + t) * 128 + n * 2);
            *(bf16*)(dsm + SOAH + sw) = h;
            *(bf16*)(dsm + SOAL + sw) = l;
        }
    }

    // ---- MMA phase: 8 N-chunks of 128 cols ----
    for (int nc = 0; nc < 8; ++nc) {
        const int buf = nc & 1;
        if (nc + 1 < 8) {
            stageB(nc + 1, buf ^ 1);
            CPA_COMMIT();
            CPA_WAIT1();
        } else {
            CPA_WAIT0();
        }
        __syncthreads();   // B(buf) ready; also covers A-tile visibility (nc=0)

        float acc[2][8][4];
#pragma unroll
        for (int mt = 0; mt < 2; ++mt)
#pragma unroll
            for (int nt = 0; nt < 8; ++nt)
#pragma unroll
                for (int q = 0; q < 4; ++q) acc[mt][nt][q] = 0.f;

#pragma unroll
        for (int ks = 0; ks < 4; ++ks) {
            u32 ah[2][4], al[2][4], bh[8][2], bl[8][2];
#pragma unroll
            for (int mt = 0; mt < 2; ++mt) {
                u32 off = SW128((mw + mt * 16 + arow) * 128 + (ks * 16 + acol) * 2);
                LDSM4(ah[mt], sbase + SOAH + off);
                LDSM4(al[mt], sbase + SOAL + off);
            }
#pragma unroll
            for (int nt = 0; nt < 8; ++nt) {
                int col = nw + nt * 8;
                u32 off = (u32)(col >> 6) * 8192 +
                          SW128((ks * 16 + brow) * 128 + (col & 63) * 2);
                LDSM2T(bh[nt], sbase + SOBH(buf) + off);
                LDSM2T(bl[nt], sbase + SOBL(buf) + off);
            }
#pragma unroll
            for (int mt = 0; mt < 2; ++mt)
#pragma unroll
                for (int nt = 0; nt < 8; ++nt) {
                    MMA(acc[mt][nt], ah[mt], bh[nt]);
                    MMA(acc[mt][nt], ah[mt], bl[nt]);
                    MMA(acc[mt][nt], al[mt], bh[nt]);
                }
        }

#pragma unroll
        for (int mt = 0; mt < 2; ++mt)
#pragma unroll
            for (int nt = 0; nt < 8; ++nt) {
                int r0 = m0 + mw + mt * 16 + (lane >> 2);
                int col = nc * 128 + nw + nt * 8 + 2 * (lane & 3);
                float b0v = bo[col], b1v = bo[col + 1];
                *(float2*)&out[(size_t)r0 * DD + col] =
                    make_float2(acc[mt][nt][0] + b0v, acc[mt][nt][1] + b1v);
                *(float2*)&out[(size_t)(r0 + 8) * DD + col] =
                    make_float2(acc[mt][nt][2] + b0v, acc[mt][nt][3] + b1v);
            }
        // REQUIRED: next iteration's stageB overwrites the buffer read above.
        __syncthreads();
    }
}

// ---------------- launch ----------------
extern "C" void kernel_launch(void* const* d_in, const int* in_sizes, int n_in,
                              void* d_out, int out_size)
{
    const float* x      = (const float*)d_in[0];
    const float* conv_w = (const float*)d_in[1];
    const float* conv_b = (const float*)d_in[2];
    const float* Wp     = (const float*)d_in[3];
    const float* bp     = (const float*)d_in[4];
    const float* Ws     = (const float*)d_in[5];
    const float* bs     = (const float*)d_in[6];
    const float* A_log  = (const float*)d_in[7];
    const float* dt_log = (const float*)d_in[8];
    const float* Wo     = (const float*)d_in[9];
    const float* bo     = (const float*)d_in[10];
    float* out = (float*)d_out;

    float *p_p, *ct_p, *carry_p, *ebias_p, *sd_p;
    cudaGetSymbolAddress((void**)&p_p,     g_P);
    cudaGetSymbolAddress((void**)&ct_p,    g_Ct);
    cudaGetSymbolAddress((void**)&carry_p, g_carryT);
    cudaGetSymbolAddress((void**)&ebias_p, g_ebias);
    cudaGetSymbolAddress((void**)&sd_p,    g_sd);

    static int attr_done = 0;
    if (!attr_done) {
        cudaFuncSetAttribute(tc_fused, cudaFuncAttributeMaxDynamicSharedMemorySize, FUSED_SMEM);
        cudaFuncSetAttribute(tc_scan_out, cudaFuncAttributeMaxDynamicSharedMemorySize, SCANOUT_SMEM);
        attr_done = 1;
    }

    // 0) weights -> bf16 hi/lo, effective biases, scan constants
    prep_kernel<<<64, 256>>>(Wp, Ws, Wo, conv_b, bp, bs, A_log, dt_log, ebias_p, sd_p);

    // 1) fused conv + gate GEMM + u GEMM -> P, Ct, chunk partials
    tc_fused<<<MM / 64, 384, FUSED_SMEM>>>(x, conv_w, ebias_p, sd_p);

    // 2) carry combine (exclusive carries in place)
    scan_carry<<<32, 256>>>(sd_p, carry_p);

    // 3) fused scan_final + output GEMM
    tc_scan_out<<<MM / 128, 256, SCANOUT_SMEM>>>(p_p, ct_p, sd_p, carry_p, bo, out);
}

// round 15
// speedup vs baseline: 1.0105x; 1.0105x over previous
#include <cuda_runtime.h>
#include <cuda_bf16.h>
#include <math.h>
#include <stdint.h>

// Problem dims (fixed by the dataset)
#define BB 4
#define LL 4096
#define DD 1024
#define NN 64
#define MM (BB * LL)
#define NCH 512
#define TCH (LL / NCH)    // 8

typedef unsigned int u32;
typedef __nv_bfloat16 bf16;

// ---------------- scratch (device globals: no allocation allowed) ----------------
__device__ bf16 g_WpH[DD * 2 * NN], g_WpL[DD * 2 * NN];   // [1024][128]
__device__ bf16 g_WsH[DD * NN],     g_WsL[DD * NN];       // [1024][64]
__device__ bf16 g_WoH[NN * DD],     g_WoL[NN * DD];       // [64][1024]
__device__ float g_P [MM * NN];                            // dt * Bt * u
__device__ float g_Ct[MM * NN];
__device__ bf16  g_yH[MM * NN], g_yL[MM * NN];            // [16384][64]
__device__ float g_carryT[BB * NN * NCH];                 // transposed partials
__device__ float g_ebias[3 * NN];
__device__ float g_sd[3 * NN];                            // dt | decay | decay^TCH

// ---------------- helpers ----------------
#define SW128(o) ((u32)(o) ^ ((((u32)(o)) >> 3) & 0x70))

__device__ __forceinline__ u32 s2u(const void* p) {
    u32 a;
    asm("{ .reg .u64 t; cvta.to.shared.u64 t, %1; cvt.u32.u64 %0, t; }" : "=r"(a) : "l"(p));
    return a;
}
__device__ __forceinline__ float sp(float v) { return v > 20.f ? v : log1pf(expf(v)); }

#define LDSM4(r, a)                                                                    \
    asm volatile("ldmatrix.sync.aligned.m8n8.x4.shared.b16 {%0,%1,%2,%3}, [%4];"      \
                 : "=r"((r)[0]), "=r"((r)[1]), "=r"((r)[2]), "=r"((r)[3]) : "r"(a))
#define LDSM2T(r, a)                                                                   \
    asm volatile("ldmatrix.sync.aligned.m8n8.x2.trans.shared.b16 {%0,%1}, [%2];"      \
                 : "=r"((r)[0]), "=r"((r)[1]) : "r"(a))
#define MMA(d, a, b)                                                                   \
    asm volatile("mma.sync.aligned.m16n8k16.row.col.f32.bf16.bf16.f32 "               \
                 "{%0,%1,%2,%3}, {%4,%5,%6,%7}, {%8,%9}, {%0,%1,%2,%3};"              \
                 : "+f"((d)[0]), "+f"((d)[1]), "+f"((d)[2]), "+f"((d)[3])             \
                 : "r"((a)[0]), "r"((a)[1]), "r"((a)[2]), "r"((a)[3]),                \
                   "r"((b)[0]), "r"((b)[1]))

#define CPA16(sa, gp)                                                                  \
    asm volatile("cp.async.cg.shared.global [%0], [%1], 16;" :: "r"((u32)(sa)), "l"(gp))
#define CPA_COMMIT() asm volatile("cp.async.commit_group;" ::: "memory")
#define CPA_WAIT1()  asm volatile("cp.async.wait_group 1;" ::: "memory")
#define CPA_WAIT0()  asm volatile("cp.async.wait_group 0;" ::: "memory")

__device__ __forceinline__ void split1(float v, bf16& h, bf16& l) {
    h = __float2bfloat16(v);
    l = __float2bfloat16(v - __bfloat162float(h));
}
__device__ __forceinline__ void split_store8(char* hiP, char* loP, float4 v) {
    bf16 h0, l0, h1, l1, h2, l2, h3, l3;
    split1(v.x, h0, l0); split1(v.y, h1, l1);
    split1(v.z, h2, l2); split1(v.w, h3, l3);
    __nv_bfloat162 hp0 = {h0, h1}, hp1 = {h2, h3};
    __nv_bfloat162 lp0 = {l0, l1}, lp1 = {l2, l3};
    *(uint2*)hiP = make_uint2(*(u32*)&hp0, *(u32*)&hp1);
    *(uint2*)loP = make_uint2(*(u32*)&lp0, *(u32*)&lp1);
}
__device__ __forceinline__ float4 f4fma(float4 acc, float4 a, float4 b) {
    acc.x = fmaf(a.x, b.x, acc.x); acc.y = fmaf(a.y, b.y, acc.y);
    acc.z = fmaf(a.z, b.z, acc.z); acc.w = fmaf(a.w, b.w, acc.w);
    return acc;
}

// ---------------- kernel 0: weight bf16 hi/lo split + ebias + scan consts --------
__global__ void __launch_bounds__(256) prep_kernel(
    const float* __restrict__ Wp, const float* __restrict__ Ws,
    const float* __restrict__ Wo, const float* __restrict__ cb,
    const float* __restrict__ bp, const float* __restrict__ bs,
    const float* __restrict__ A_log, const float* __restrict__ dt_log,
    float* __restrict__ ebias, float* __restrict__ sd)
{
    const int gtid = blockIdx.x * 256 + threadIdx.x;
    const int NT = gridDim.x * 256;

    for (int i = gtid; i < DD * 2 * NN; i += NT) split1(Wp[i], g_WpH[i], g_WpL[i]);
    for (int i = gtid; i < DD * NN;     i += NT) split1(Ws[i], g_WsH[i], g_WsL[i]);
    for (int i = gtid; i < NN * DD;     i += NT) split1(Wo[i], g_WoH[i], g_WoL[i]);

    if (gtid < 2 * NN) {
        float s = bp[gtid];
#pragma unroll 8
        for (int d = 0; d < DD; ++d) s = fmaf(cb[d], Wp[(size_t)d * 2 * NN + gtid], s);
        ebias[gtid] = s;
    } else if (gtid < 3 * NN) {
        ebias[gtid] = bs[gtid - 2 * NN];
    } else if (gtid < 3 * NN + NN) {
        int n = gtid - 3 * NN;
        float dt = sp(dt_log[n]);
        float decay = 1.f - dt * sp(A_log[n]);
        float dp = decay;
#pragma unroll
        for (int i = 0; i < 3; ++i) dp *= dp;      // decay^8 (TCH = 2^3)
        sd[n] = dt;
        sd[NN + n] = decay;
        sd[2 * NN + n] = dp;
    }
}

// ---------------- kernel 1: fused conv + gates + u -> P, Ct, chunk partials ------
#define FX(b)   (0      + (b) * 17408)   // raw x: 67 rows x 256B
#define FBPH(b) (34816  + (b) * 16384)   // Wp hi: 64x128 bf16, 2 panels SW128
#define FBPL(b) (67584  + (b) * 16384)
#define FBSH(b) (100352 + (b) * 8192)    // Ws hi: 64x64 bf16 SW128
#define FBSL(b) (116736 + (b) * 8192)
#define FACH(b) (133120 + (b) * 8192)    // conv split hi
#define FACL(b) (149504 + (b) * 8192)
#define FAXH(b) (165888 + (b) * 8192)    // x split hi
#define FAXL(b) (182272 + (b) * 8192)
#define FUSED_SMEM 198656
#define USTRIDE 66                       // u / P exchange row stride (floats)

__global__ void __launch_bounds__(384, 1) tc_fused(
    const float* __restrict__ x, const float* __restrict__ cw,
    const float* __restrict__ ebias, const float* __restrict__ sd)
{
    extern __shared__ char dsm[];
    const int tid = threadIdx.x;
    const int lane = tid & 31, w = tid >> 5;
    const int m0 = blockIdx.x * 64;
    const bool seqstart = ((m0 & (LL - 1)) == 0);

    const bool is_gate = (w < 8);
    const int mw = is_gate ? ((w >> 2) * 32) : (((w - 8) >> 1) * 32);
    const int nw = is_gate ? ((w & 3) * 32) : (((w - 8) & 1) * 32);

    float acc[2][4][4];
#pragma unroll
    for (int mt = 0; mt < 2; ++mt)
#pragma unroll
        for (int nt = 0; nt < 4; ++nt)
#pragma unroll
            for (int q = 0; q < 4; ++q) acc[mt][nt][q] = 0.f;

    const int arow = lane & 15, acol = (lane >> 4) * 8;
    const int brow = lane & 15;

    const u32 sbase = s2u(dsm);

    auto stage = [&](int kt, int buf) {
        for (int i = tid; i < 67 * 16; i += 384) {
            int rr = i >> 4, ch = i & 15;
            u32 dst = sbase + FX(buf) + rr * 256 + ch * 16;
            if (seqstart && rr < 3) {
                *(uint4*)(dsm + FX(buf) + rr * 256 + ch * 16) = make_uint4(0, 0, 0, 0);
            } else {
                CPA16(dst, x + (size_t)(m0 - 3 + rr) * DD + kt * 64 + ch * 4);
            }
        }
        for (int i = tid; i < 64 * 16; i += 384) {
            int r = i >> 4, ch = i & 15;
            size_t gb = (size_t)(kt * 64 + r) * 256 + ch * 16;
            u32 sw = (u32)(ch >> 3) * 8192 + SW128(r * 128 + (ch & 7) * 16);
            CPA16(sbase + FBPH(buf) + sw, (const char*)g_WpH + gb);
            CPA16(sbase + FBPL(buf) + sw, (const char*)g_WpL + gb);
        }
        for (int i = tid; i < 64 * 8; i += 384) {
            int r = i >> 3, ch = i & 7;
            size_t gb = (size_t)(kt * 64 + r) * 128 + ch * 16;
            u32 sw = SW128(r * 128 + ch * 16);
            CPA16(sbase + FBSH(buf) + sw, (const char*)g_WsH + gb);
            CPA16(sbase + FBSL(buf) + sw, (const char*)g_WsL + gb);
        }
    };

    stage(0, 0);
    CPA_COMMIT();

    for (int kt = 0; kt < DD / 64; ++kt) {
        const int buf = kt & 1;
        if (kt + 1 < DD / 64) {
            stage(kt + 1, buf ^ 1);
            CPA_COMMIT();
            CPA_WAIT1();
        } else {
            CPA_WAIT0();
        }
        __syncthreads();

        // ---- conv + split -> sAc(buf); raw x split -> sAx(buf) ----
        char* sX = dsm + FX(buf);
#pragma unroll
        for (int i = tid; i < 64 * 16; i += 384) {
            int r = i >> 4, ch = i & 15;
            float4 xm3 = *(const float4*)(sX + (r + 0) * 256 + ch * 16);
            float4 xm2 = *(const float4*)(sX + (r + 1) * 256 + ch * 16);
            float4 xm1 = *(const float4*)(sX + (r + 2) * 256 + ch * 16);
            float4 xc  = *(const float4*)(sX + (r + 3) * 256 + ch * 16);
            int dcol = kt * 64 + ch * 4;
            float4 w0 = *(const float4*)(cw + 0 * DD + dcol);
            float4 w1 = *(const float4*)(cw + 1 * DD + dcol);
            float4 w2 = *(const float4*)(cw + 2 * DD + dcol);
            float4 w3 = *(const float4*)(cw + 3 * DD + dcol);
            float4 o = make_float4(0.f, 0.f, 0.f, 0.f);
            o = f4fma(o, w0, xm3); o = f4fma(o, w1, xm2);
            o = f4fma(o, w2, xm1); o = f4fma(o, w3, xc);
            u32 sw = SW128(r * 128 + ch * 8);
            split_store8(dsm + FACH(buf) + sw, dsm + FACL(buf) + sw, o);
            split_store8(dsm + FAXH(buf) + sw, dsm + FAXL(buf) + sw, xc);
        }
        __syncthreads();

        // ---- MMA ----
        const u32 aH = sbase + (is_gate ? FACH(buf) : FAXH(buf));
        const u32 aL = sbase + (is_gate ? FACL(buf) : FAXL(buf));
        const u32 bH = sbase + (is_gate ? FBPH(buf) : FBSH(buf));
        const u32 bL = sbase + (is_gate ? FBPL(buf) : FBSL(buf));
#pragma unroll
        for (int ks = 0; ks < 4; ++ks) {
            u32 ah[2][4], al[2][4], bh[4][2], bl[4][2];
#pragma unroll
            for (int mt = 0; mt < 2; ++mt) {
                u32 off = SW128((mw + mt * 16 + arow) * 128 + (ks * 16 + acol) * 2);
                LDSM4(ah[mt], aH + off);
                LDSM4(al[mt], aL + off);
            }
#pragma unroll
            for (int nt = 0; nt < 4; ++nt) {
                int col = nw + nt * 8;
                u32 off = (u32)(col >> 6) * 8192 +
                          SW128((ks * 16 + brow) * 128 + (col & 63) * 2);
                LDSM2T(bh[nt], bH + off);
                LDSM2T(bl[nt], bL + off);
            }
#pragma unroll
            for (int mt = 0; mt < 2; ++mt)
#pragma unroll
                for (int nt = 0; nt < 4; ++nt) {
                    MMA(acc[mt][nt], ah[mt], bh[nt]);
                    MMA(acc[mt][nt], ah[mt], bl[nt]);
                    MMA(acc[mt][nt], al[mt], bh[nt]);
                }
        }
        // REQUIRED: next iteration's stage() overwrites buffers read above.
        __syncthreads();
    }

    // ---- epilogue: u warps -> smem exchange; gate warps -> P (gmem + smem), Ct --
    float* sU = (float*)dsm;                 // FX(0) region
    float* sP = (float*)(dsm + 17408);       // FX(1) region
    if (!is_gate) {
#pragma unroll
        for (int mt = 0; mt < 2; ++mt)
#pragma unroll
            for (int nt = 0; nt < 4; ++nt) {
                int r = mw + mt * 16 + (lane >> 2);
                int col = nw + nt * 8 + 2 * (lane & 3);
                float b0v = ebias[2 * NN + col], b1v = ebias[2 * NN + col + 1];
                sU[r * USTRIDE + col]           = acc[mt][nt][0] + b0v;
                sU[r * USTRIDE + col + 1]       = acc[mt][nt][1] + b1v;
                sU[(r + 8) * USTRIDE + col]     = acc[mt][nt][2] + b0v;
                sU[(r + 8) * USTRIDE + col + 1] = acc[mt][nt][3] + b1v;
            }
    }
    __syncthreads();
    if (is_gate) {
#pragma unroll
        for (int mt = 0; mt < 2; ++mt)
#pragma unroll
            for (int nt = 0; nt < 4; ++nt) {
                int r = mw + mt * 16 + (lane >> 2);
                int col = nw + nt * 8 + 2 * (lane & 3);
                float b0v = ebias[col], b1v = ebias[col + 1];
                float vx = acc[mt][nt][0] + b0v, vy = acc[mt][nt][1] + b1v;
                float vz = acc[mt][nt][2] + b0v, vw = acc[mt][nt][3] + b1v;
                if (col < 64) {
                    float dt0 = sd[col], dt1 = sd[col + 1];
                    float p0 = dt0 * sp(vx) * sU[r * USTRIDE + col];
                    float p1 = dt1 * sp(vy) * sU[r * USTRIDE + col + 1];
                    float p2 = dt0 * sp(vz) * sU[(r + 8) * USTRIDE + col];
                    float p3 = dt1 * sp(vw) * sU[(r + 8) * USTRIDE + col + 1];
                    *(float2*)&g_P[(size_t)(m0 + r) * NN + col] = make_float2(p0, p1);
                    *(float2*)&g_P[(size_t)(m0 + r + 8) * NN + col] = make_float2(p2, p3);
                    sP[r * USTRIDE + col]           = p0;
                    sP[r * USTRIDE + col + 1]       = p1;
                    sP[(r + 8) * USTRIDE + col]     = p2;
                    sP[(r + 8) * USTRIDE + col + 1] = p3;
                } else {
                    vx = tanhf(vx); vy = tanhf(vy); vz = tanhf(vz); vw = tanhf(vw);
                    *(float2*)&g_Ct[(size_t)(m0 + r) * NN + col - 64] = make_float2(vx, vy);
                    *(float2*)&g_Ct[(size_t)(m0 + r + 8) * NN + col - 64] = make_float2(vz, vw);
                }
            }
    }
    __syncthreads();

    // ---- fused scan_partial: 8 chunks x 64 n over this block's 64 rows ----
    {
        const int bb = m0 >> 12;                       // m0 / LL
        const int ch0 = (m0 & (LL - 1)) >> 3;          // first chunk index
        for (int pair = tid; pair < 8 * 64; pair += 384) {
            int ch_l = pair >> 6, n = pair & 63;
            float decay = sd[NN + n];
            float s = 0.f;
#pragma unroll
            for (int t = 0; t < 8; ++t)
                s = fmaf(decay, s, sP[(ch_l * 8 + t) * USTRIDE + n]);
            g_carryT[((size_t)bb * NN + n) * NCH + ch0 + ch_l] = s;
        }
    }
}

// ---------------- kernel 2: scan_carry (warp-parallel, Kogge-Stone) ----------
__global__ void __launch_bounds__(256) scan_carry(
    const float* __restrict__ sd, float* __restrict__ carryT)
{
    const int wid = threadIdx.x >> 5, lane = threadIdx.x & 31;
    const int row = blockIdx.x * 8 + wid;          // 0..255 = b*NN + n
    const int n = row & (NN - 1);
    const float dp = sd[2 * NN + n];

    float4* p = (float4*)(carryT + (size_t)row * NCH) + lane * 4;
    float4 e0 = p[0], e1 = p[1], e2 = p[2], e3 = p[3];

    float l[16];
    l[0]  = e0.x;
    l[1]  = fmaf(dp, l[0],  e0.y);
    l[2]  = fmaf(dp, l[1],  e0.z);
    l[3]  = fmaf(dp, l[2],  e0.w);
    l[4]  = fmaf(dp, l[3],  e1.x);
    l[5]  = fmaf(dp, l[4],  e1.y);
    l[6]  = fmaf(dp, l[5],  e1.z);
    l[7]  = fmaf(dp, l[6],  e1.w);
    l[8]  = fmaf(dp, l[7],  e2.x);
    l[9]  = fmaf(dp, l[8],  e2.y);
    l[10] = fmaf(dp, l[9],  e2.z);
    l[11] = fmaf(dp, l[10], e2.w);
    l[12] = fmaf(dp, l[11], e3.x);
    l[13] = fmaf(dp, l[12], e3.y);
    l[14] = fmaf(dp, l[13], e3.z);
    l[15] = fmaf(dp, l[14], e3.w);

    const float dp2 = dp * dp, dp4 = dp2 * dp2, dp8 = dp4 * dp4, dp16 = dp8 * dp8;
    float s = l[15], f = dp16;
#pragma unroll
    for (int k = 1; k < 32; k <<= 1) {
        float t = __shfl_up_sync(0xffffffffu, s, k);
        if (lane >= k) s = fmaf(f, t, s);
        f = f * f;
    }
    float prev = __shfl_up_sync(0xffffffffu, s, 1);
    if (lane == 0) prev = 0.f;

    float c[16];
    c[0] = prev;
    float dpj = dp;
#pragma unroll
    for (int j = 1; j < 16; ++j) {
        c[j] = fmaf(dpj, prev, l[j - 1]);
        dpj *= dp;
    }
    p[0] = make_float4(c[0],  c[1],  c[2],  c[3]);
    p[1] = make_float4(c[4],  c[5],  c[6],  c[7]);
    p[2] = make_float4(c[8],  c[9],  c[10], c[11]);
    p[3] = make_float4(c[12], c[13], c[14], c[15]);
}

// ---------------- kernel 3: scan_final -> y bf16 hi/lo ----------------
__global__ void __launch_bounds__(256) scan_final(
    const float* __restrict__ P, const float* __restrict__ Ct,
    const float* __restrict__ sd, const float* __restrict__ carryT)
{
    const int n = threadIdx.x & 63;
    const int ch = blockIdx.x * 4 + (threadIdx.x >> 6);
    const int b = blockIdx.y;
    const float decay = sd[NN + n];
    size_t base = ((size_t)b * LL + (size_t)ch * TCH) * NN + n;
    float s = carryT[((size_t)b * NN + n) * NCH + ch];
#pragma unroll
    for (int t = 0; t < TCH; ++t) {
        size_t idx = base + (size_t)t * NN;
        s = fmaf(decay, s, P[idx]);
        float yv = Ct[idx] * s;
        split1(yv, g_yH[idx], g_yL[idx]);
    }
}

// ---------------- kernel 4: out = y @ Wo + bo (M-tile 128, N-tile 128, K=64) -----
#define OAH 0
#define OAL 16384
#define OBH 32768
#define OBL 49152
#define TCOUT_SMEM 65536

__global__ void __launch_bounds__(256) tc_out(
    const float* __restrict__ bo, float* __restrict__ out)
{
    extern __shared__ char dsm[];
    const int tid = threadIdx.x;
    const int lane = tid & 31, w = tid >> 5;
    const int mw = (w >> 1) * 32;        // 4 m-warps
    const int nw = (w & 1) * 64;         // 2 n-warps
    const int m0 = blockIdx.x * 128;
    const int n0 = blockIdx.y * 128;

    const u32 sbase = s2u(dsm);
    const int arow = lane & 15, acol = (lane >> 4) * 8;
    const int brow = lane & 15;

#pragma unroll
    for (int i = tid; i < 128 * 8; i += 256) {
        int r = i >> 3, ch = i & 7;
        size_t gb = (size_t)(m0 + r) * 128 + ch * 16;
        u32 sw = SW128(r * 128 + ch * 16);
        CPA16(sbase + OAH + sw, (const char*)g_yH + gb);
        CPA16(sbase + OAL + sw, (const char*)g_yL + gb);
    }
#pragma unroll
    for (int i = tid; i < 64 * 16; i += 256) {
        int r = i >> 4, ch = i & 15;
        size_t gb = (size_t)r * 2048 + (size_t)n0 * 2 + ch * 16;
        u32 sw = (u32)(ch >> 3) * 8192 + SW128(r * 128 + (ch & 7) * 16);
        CPA16(sbase + OBH + sw, (const char*)g_WoH + gb);
        CPA16(sbase + OBL + sw, (const char*)g_WoL + gb);
    }
    CPA_COMMIT();
    CPA_WAIT0();
    __syncthreads();

    float acc[2][8][4];
#pragma unroll
    for (int mt = 0; mt < 2; ++mt)
#pragma unroll
        for (int nt = 0; nt < 8; ++nt)
#pragma unroll
            for (int q = 0; q < 4; ++q) acc[mt][nt][q] = 0.f;

#pragma unroll
    for (int ks = 0; ks < 4; ++ks) {
        u32 ah[2][4], al[2][4], bh[8][2], bl[8][2];
#pragma unroll
        for (int mt = 0; mt < 2; ++mt) {
            u32 off = SW128((mw + mt * 16 + arow) * 128 + (ks * 16 + acol) * 2);
            LDSM4(ah[mt], sbase + OAH + off);
            LDSM4(al[mt], sbase + OAL + off);
        }
#pragma unroll
        for (int nt = 0; nt < 8; ++nt) {
            int col = nw + nt * 8;
            u32 off = (u32)(col >> 6) * 8192 +
                      SW128((ks * 16 + brow) * 128 + (col & 63) * 2);
            LDSM2T(bh[nt], sbase + OBH + off);
            LDSM2T(bl[nt], sbase + OBL + off);
        }
#pragma unroll
        for (int mt = 0; mt < 2; ++mt)
#pragma unroll
            for (int nt = 0; nt < 8; ++nt) {
                MMA(acc[mt][nt], ah[mt], bh[nt]);
                MMA(acc[mt][nt], ah[mt], bl[nt]);
                MMA(acc[mt][nt], al[mt], bh[nt]);
            }
    }

#pragma unroll
    for (int mt = 0; mt < 2; ++mt)
#pragma unroll
        for (int nt = 0; nt < 8; ++nt) {
            int r0 = m0 + mw + mt * 16 + (lane >> 2);
            int col = n0 + nw + nt * 8 + 2 * (lane & 3);
            float b0v = bo[col], b1v = bo[col + 1];
            *(float2*)&out[(size_t)r0 * DD + col] =
                make_float2(acc[mt][nt][0] + b0v, acc[mt][nt][1] + b1v);
            *(float2*)&out[(size_t)(r0 + 8) * DD + col] =
                make_float2(acc[mt][nt][2] + b0v, acc[mt][nt][3] + b1v);
        }
}

// ---------------- launch ----------------
extern "C" void kernel_launch(void* const* d_in, const int* in_sizes, int n_in,
                              void* d_out, int out_size)
{
    const float* x      = (const float*)d_in[0];
    const float* conv_w = (const float*)d_in[1];
    const float* conv_b = (const float*)d_in[2];
    const float* Wp     = (const float*)d_in[3];
    const float* bp     = (const float*)d_in[4];
    const float* Ws     = (const float*)d_in[5];
    const float* bs     = (const float*)d_in[6];
    const float* A_log  = (const float*)d_in[7];
    const float* dt_log = (const float*)d_in[8];
    const float* Wo     = (const float*)d_in[9];
    const float* bo     = (const float*)d_in[10];
    float* out = (float*)d_out;

    float *p_p, *ct_p, *carry_p, *ebias_p, *sd_p;
    cudaGetSymbolAddress((void**)&p_p,     g_P);
    cudaGetSymbolAddress((void**)&ct_p,    g_Ct);
    cudaGetSymbolAddress((void**)&carry_p, g_carryT);
    cudaGetSymbolAddress((void**)&ebias_p, g_ebias);
    cudaGetSymbolAddress((void**)&sd_p,    g_sd);

    static int attr_done = 0;
    if (!attr_done) {
        cudaFuncSetAttribute(tc_fused, cudaFuncAttributeMaxDynamicSharedMemorySize, FUSED_SMEM);
        cudaFuncSetAttribute(tc_out, cudaFuncAttributeMaxDynamicSharedMemorySize, TCOUT_SMEM);
        attr_done = 1;
    }

    // 0) weights -> bf16 hi/lo, effective biases, scan constants
    prep_kernel<<<64, 256>>>(Wp, Ws, Wo, conv_b, bp, bs, A_log, dt_log, ebias_p, sd_p);

    // 1) fused conv + gate GEMM + u GEMM -> P, Ct, chunk partials
    tc_fused<<<MM / 64, 384, FUSED_SMEM>>>(x, conv_w, ebias_p, sd_p);

    // 2) carry combine (exclusive carries in place)
    scan_carry<<<32, 256>>>(sd_p, carry_p);

    // 3) scan_final -> y (bf16 hi/lo)
    scan_final<<<dim3(NCH / 4, BB), 256>>>(p_p, ct_p, sd_p, carry_p);

    // 4) out = y @ Wo + bo (M-tile 128, N-tile 128; 1024 blocks)
    tc_out<<<dim3(MM / 128, DD / 128), 256, TCOUT_SMEM>>>(bo, out);
}

// round 16
// speedup vs baseline: 1.1312x; 1.1194x over previous
#include <cuda_runtime.h>
#include <cuda_bf16.h>
#include <math.h>
#include <stdint.h>

// Problem dims (fixed by the dataset)
#define BB 4
#define LL 4096
#define DD 1024
#define NN 64
#define MM (BB * LL)
#define NCH 512
#define TCH (LL / NCH)    // 8

typedef unsigned int u32;
typedef __nv_bfloat16 bf16;

// ---------------- scratch (device globals: no allocation allowed) ----------------
__device__ bf16 g_WpH[DD * 2 * NN], g_WpL[DD * 2 * NN];   // [1024][128]
__device__ bf16 g_WsH[DD * NN],     g_WsL[DD * NN];       // [1024][64]
__device__ bf16 g_WoH[NN * DD],     g_WoL[NN * DD];       // [64][1024]
__device__ float g_P [MM * NN];                            // dt * Bt * u
__device__ float g_Ct[MM * NN];
__device__ bf16  g_yH[MM * NN], g_yL[MM * NN];            // [16384][64]
__device__ float g_carryT[BB * NN * NCH];                 // transposed partials
__device__ float g_ebias[3 * NN];
__device__ float g_sd[3 * NN];                            // dt | decay | decay^TCH

// ---------------- helpers ----------------
#define SW128(o) ((u32)(o) ^ ((((u32)(o)) >> 3) & 0x70))

__device__ __forceinline__ u32 s2u(const void* p) {
    u32 a;
    asm("{ .reg .u64 t; cvta.to.shared.u64 t, %1; cvt.u32.u64 %0, t; }" : "=r"(a) : "l"(p));
    return a;
}
__device__ __forceinline__ float sp(float v) { return v > 20.f ? v : log1pf(expf(v)); }

#define LDSM4(r, a)                                                                    \
    asm volatile("ldmatrix.sync.aligned.m8n8.x4.shared.b16 {%0,%1,%2,%3}, [%4];"      \
                 : "=r"((r)[0]), "=r"((r)[1]), "=r"((r)[2]), "=r"((r)[3]) : "r"(a))
#define LDSM2T(r, a)                                                                   \
    asm volatile("ldmatrix.sync.aligned.m8n8.x2.trans.shared.b16 {%0,%1}, [%2];"      \
                 : "=r"((r)[0]), "=r"((r)[1]) : "r"(a))
#define MMA(d, a, b)                                                                   \
    asm volatile("mma.sync.aligned.m16n8k16.row.col.f32.bf16.bf16.f32 "               \
                 "{%0,%1,%2,%3}, {%4,%5,%6,%7}, {%8,%9}, {%0,%1,%2,%3};"              \
                 : "+f"((d)[0]), "+f"((d)[1]), "+f"((d)[2]), "+f"((d)[3])             \
                 : "r"((a)[0]), "r"((a)[1]), "r"((a)[2]), "r"((a)[3]),                \
                   "r"((b)[0]), "r"((b)[1]))

#define CPA16(sa, gp)                                                                  \
    asm volatile("cp.async.cg.shared.global [%0], [%1], 16;" :: "r"((u32)(sa)), "l"(gp))
#define CPA_COMMIT() asm volatile("cp.async.commit_group;" ::: "memory")
#define CPA_WAIT0()  asm volatile("cp.async.wait_group 0;" ::: "memory")

__device__ __forceinline__ void split1(float v, bf16& h, bf16& l) {
    h = __float2bfloat16(v);
    l = __float2bfloat16(v - __bfloat162float(h));
}
__device__ __forceinline__ void split_store8(char* hiP, char* loP, float4 v) {
    bf16 h0, l0, h1, l1, h2, l2, h3, l3;
    split1(v.x, h0, l0); split1(v.y, h1, l1);
    split1(v.z, h2, l2); split1(v.w, h3, l3);
    __nv_bfloat162 hp0 = {h0, h1}, hp1 = {h2, h3};
    __nv_bfloat162 lp0 = {l0, l1}, lp1 = {l2, l3};
    *(uint2*)hiP = make_uint2(*(u32*)&hp0, *(u32*)&hp1);
    *(uint2*)loP = make_uint2(*(u32*)&lp0, *(u32*)&lp1);
}
__device__ __forceinline__ float4 f4fma(float4 acc, float4 a, float4 b) {
    acc.x = fmaf(a.x, b.x, acc.x); acc.y = fmaf(a.y, b.y, acc.y);
    acc.z = fmaf(a.z, b.z, acc.z); acc.w = fmaf(a.w, b.w, acc.w);
    return acc;
}

// ---------------- kernel 0: weight bf16 hi/lo split + ebias + scan consts --------
__global__ void __launch_bounds__(256) prep_kernel(
    const float* __restrict__ Wp, const float* __restrict__ Ws,
    const float* __restrict__ Wo, const float* __restrict__ cb,
    const float* __restrict__ bp, const float* __restrict__ bs,
    const float* __restrict__ A_log, const float* __restrict__ dt_log,
    float* __restrict__ ebias, float* __restrict__ sd)
{
    const int gtid = blockIdx.x * 256 + threadIdx.x;
    const int NT = gridDim.x * 256;

    for (int i = gtid; i < DD * 2 * NN; i += NT) split1(Wp[i], g_WpH[i], g_WpL[i]);
    for (int i = gtid; i < DD * NN;     i += NT) split1(Ws[i], g_WsH[i], g_WsL[i]);
    for (int i = gtid; i < NN * DD;     i += NT) split1(Wo[i], g_WoH[i], g_WoL[i]);

    if (gtid < 2 * NN) {
        float s = bp[gtid];
#pragma unroll 8
        for (int d = 0; d < DD; ++d) s = fmaf(cb[d], Wp[(size_t)d * 2 * NN + gtid], s);
        ebias[gtid] = s;
    } else if (gtid < 3 * NN) {
        ebias[gtid] = bs[gtid - 2 * NN];
    } else if (gtid < 3 * NN + NN) {
        int n = gtid - 3 * NN;
        float dt = sp(dt_log[n]);
        float decay = 1.f - dt * sp(A_log[n]);
        float dp = decay;
#pragma unroll
        for (int i = 0; i < 3; ++i) dp *= dp;      // decay^8 (TCH = 2^3)
        sd[n] = dt;
        sd[NN + n] = decay;
        sd[2 * NN + n] = dp;
    }
}

// ---------------- kernel 1: fused conv + gates + u -> P, Ct, chunk partials ------
// SINGLE-buffered smem (99 KB) -> 2 blocks/SM, grid 256 = one wave.
// Pipelining via phase-ordered staging: X(kt+1) issued after conv phase
// (overlaps MMA); B(kt+1) issued after MMA barrier.
#define SFX   0          // raw x: 67 rows x 256B          (17408)
#define SBPH  17408      // Wp hi: 64x128, 2 panels SW128  (16384)
#define SBPL  33792
#define SBSH  50176      // Ws hi: 64x64 SW128             (8192)
#define SBSL  58368
#define SACH  66560      // conv split hi                  (8192)
#define SACL  74752
#define SAXH  82944      // x split hi
#define SAXL  91136
#define FUSED_SMEM 99328
#define USTRIDE 66       // u / P exchange row stride (floats)

__global__ void __launch_bounds__(384, 2) tc_fused(
    const float* __restrict__ x, const float* __restrict__ cw,
    const float* __restrict__ ebias, const float* __restrict__ sd)
{
    extern __shared__ char dsm[];
    const int tid = threadIdx.x;
    const int lane = tid & 31, w = tid >> 5;
    const int m0 = blockIdx.x * 64;
    const bool seqstart = ((m0 & (LL - 1)) == 0);

    const bool is_gate = (w < 8);
    const int mw = is_gate ? ((w >> 2) * 32) : (((w - 8) >> 1) * 32);
    const int nw = is_gate ? ((w & 3) * 32) : (((w - 8) & 1) * 32);

    float acc[2][4][4];
#pragma unroll
    for (int mt = 0; mt < 2; ++mt)
#pragma unroll
        for (int nt = 0; nt < 4; ++nt)
#pragma unroll
            for (int q = 0; q < 4; ++q) acc[mt][nt][q] = 0.f;

    const int arow = lane & 15, acol = (lane >> 4) * 8;
    const int brow = lane & 15;

    const u32 sbase = s2u(dsm);

    auto stageX = [&](int kt) {
        for (int i = tid; i < 67 * 16; i += 384) {
            int rr = i >> 4, ch = i & 15;
            if (seqstart && rr < 3) {
                *(uint4*)(dsm + SFX + rr * 256 + ch * 16) = make_uint4(0, 0, 0, 0);
            } else {
                CPA16(sbase + SFX + rr * 256 + ch * 16,
                      x + (size_t)(m0 - 3 + rr) * DD + kt * 64 + ch * 4);
            }
        }
    };
    auto stageB = [&](int kt) {
        for (int i = tid; i < 64 * 16; i += 384) {
            int r = i >> 4, ch = i & 15;
            size_t gb = (size_t)(kt * 64 + r) * 256 + ch * 16;
            u32 sw = (u32)(ch >> 3) * 8192 + SW128(r * 128 + (ch & 7) * 16);
            CPA16(sbase + SBPH + sw, (const char*)g_WpH + gb);
            CPA16(sbase + SBPL + sw, (const char*)g_WpL + gb);
        }
        for (int i = tid; i < 64 * 8; i += 384) {
            int r = i >> 3, ch = i & 7;
            size_t gb = (size_t)(kt * 64 + r) * 128 + ch * 16;
            u32 sw = SW128(r * 128 + ch * 16);
            CPA16(sbase + SBSH + sw, (const char*)g_WsH + gb);
            CPA16(sbase + SBSL + sw, (const char*)g_WsL + gb);
        }
    };

    stageX(0);
    stageB(0);
    CPA_COMMIT();

    for (int kt = 0; kt < DD / 64; ++kt) {
        CPA_WAIT0();
        __syncthreads();   // X(kt), B(kt) visible

        // ---- conv + split -> SACH/SACL; raw x split -> SAXH/SAXL ----
#pragma unroll
        for (int i = tid; i < 64 * 16; i += 384) {
            int r = i >> 4, ch = i & 15;
            float4 xm3 = *(const float4*)(dsm + SFX + (r + 0) * 256 + ch * 16);
            float4 xm2 = *(const float4*)(dsm + SFX + (r + 1) * 256 + ch * 16);
            float4 xm1 = *(const float4*)(dsm + SFX + (r + 2) * 256 + ch * 16);
            float4 xc  = *(const float4*)(dsm + SFX + (r + 3) * 256 + ch * 16);
            int dcol = kt * 64 + ch * 4;
            float4 w0 = *(const float4*)(cw + 0 * DD + dcol);
            float4 w1 = *(const float4*)(cw + 1 * DD + dcol);
            float4 w2 = *(const float4*)(cw + 2 * DD + dcol);
            float4 w3 = *(const float4*)(cw + 3 * DD + dcol);
            float4 o = make_float4(0.f, 0.f, 0.f, 0.f);
            o = f4fma(o, w0, xm3); o = f4fma(o, w1, xm2);
            o = f4fma(o, w2, xm1); o = f4fma(o, w3, xc);
            u32 sw = SW128(r * 128 + ch * 8);
            split_store8(dsm + SACH + sw, dsm + SACL + sw, o);
            split_store8(dsm + SAXH + sw, dsm + SAXL + sw, xc);
        }
        __syncthreads();   // splits ready; X no longer needed

        // stage next X now -> overlaps MMA below (single X buffer is safe:
        // all X reads completed before the barrier above)
        if (kt + 1 < DD / 64) stageX(kt + 1);

        // ---- MMA (reads splits + B) ----
        const u32 aH = sbase + (is_gate ? SACH : SAXH);
        const u32 aL = sbase + (is_gate ? SACL : SAXL);
        const u32 bH = sbase + (is_gate ? SBPH : SBSH);
        const u32 bL = sbase + (is_gate ? SBPL : SBSL);
#pragma unroll
        for (int ks = 0; ks < 4; ++ks) {
            u32 ah[2][4], al[2][4];
#pragma unroll
            for (int mt = 0; mt < 2; ++mt) {
                u32 off = SW128((mw + mt * 16 + arow) * 128 + (ks * 16 + acol) * 2);
                LDSM4(ah[mt], aH + off);
                LDSM4(al[mt], aL + off);
            }
#pragma unroll
            for (int nt = 0; nt < 4; ++nt) {
                int col = nw + nt * 8;
                u32 off = (u32)(col >> 6) * 8192 +
                          SW128((ks * 16 + brow) * 128 + (col & 63) * 2);
                u32 bh[2], bl[2];
                LDSM2T(bh, bH + off);
                LDSM2T(bl, bL + off);
#pragma unroll
                for (int mt = 0; mt < 2; ++mt) {
                    MMA(acc[mt][nt], ah[mt], bh);
                    MMA(acc[mt][nt], ah[mt], bl);
                    MMA(acc[mt][nt], al[mt], bh);
                }
            }
        }
        __syncthreads();   // all B reads done

        if (kt + 1 < DD / 64) {
            stageB(kt + 1);
            CPA_COMMIT();  // covers this iteration's X + B stages
        }
    }

    // ---- epilogue: u warps -> smem exchange; gate warps -> P (gmem + smem), Ct --
    float* sU = (float*)dsm;                 // SFX region (17408 >= 16896)
    float* sP = (float*)(dsm + SBPH);        // SBPH+SBPL region (32768 >= 16896)
    if (!is_gate) {
#pragma unroll
        for (int mt = 0; mt < 2; ++mt)
#pragma unroll
            for (int nt = 0; nt < 4; ++nt) {
                int r = mw + mt * 16 + (lane >> 2);
                int col = nw + nt * 8 + 2 * (lane & 3);
                float b0v = ebias[2 * NN + col], b1v = ebias[2 * NN + col + 1];
                sU[r * USTRIDE + col]           = acc[mt][nt][0] + b0v;
                sU[r * USTRIDE + col + 1]       = acc[mt][nt][1] + b1v;
                sU[(r + 8) * USTRIDE + col]     = acc[mt][nt][2] + b0v;
                sU[(r + 8) * USTRIDE + col + 1] = acc[mt][nt][3] + b1v;
            }
    }
    __syncthreads();
    if (is_gate) {
#pragma unroll
        for (int mt = 0; mt < 2; ++mt)
#pragma unroll
            for (int nt = 0; nt < 4; ++nt) {
                int r = mw + mt * 16 + (lane >> 2);
                int col = nw + nt * 8 + 2 * (lane & 3);
                float b0v = ebias[col], b1v = ebias[col + 1];
                float vx = acc[mt][nt][0] + b0v, vy = acc[mt][nt][1] + b1v;
                float vz = acc[mt][nt][2] + b0v, vw = acc[mt][nt][3] + b1v;
                if (col < 64) {
                    float dt0 = sd[col], dt1 = sd[col + 1];
                    float p0 = dt0 * sp(vx) * sU[r * USTRIDE + col];
                    float p1 = dt1 * sp(vy) * sU[r * USTRIDE + col + 1];
                    float p2 = dt0 * sp(vz) * sU[(r + 8) * USTRIDE + col];
                    float p3 = dt1 * sp(vw) * sU[(r + 8) * USTRIDE + col + 1];
                    *(float2*)&g_P[(size_t)(m0 + r) * NN + col] = make_float2(p0, p1);
                    *(float2*)&g_P[(size_t)(m0 + r + 8) * NN + col] = make_float2(p2, p3);
                    sP[r * USTRIDE + col]           = p0;
                    sP[r * USTRIDE + col + 1]       = p1;
                    sP[(r + 8) * USTRIDE + col]     = p2;
                    sP[(r + 8) * USTRIDE + col + 1] = p3;
                } else {
                    vx = tanhf(vx); vy = tanhf(vy); vz = tanhf(vz); vw = tanhf(vw);
                    *(float2*)&g_Ct[(size_t)(m0 + r) * NN + col - 64] = make_float2(vx, vy);
                    *(float2*)&g_Ct[(size_t)(m0 + r + 8) * NN + col - 64] = make_float2(vz, vw);
                }
            }
    }
    __syncthreads();

    // ---- fused scan_partial: 8 chunks x 64 n over this block's 64 rows ----
    {
        const int bb = m0 >> 12;                       // m0 / LL
        const int ch0 = (m0 & (LL - 1)) >> 3;          // first chunk index
        for (int pair = tid; pair < 8 * 64; pair += 384) {
            int ch_l = pair >> 6, n = pair & 63;
            float decay = sd[NN + n];
            float s = 0.f;
#pragma unroll
            for (int t = 0; t < 8; ++t)
                s = fmaf(decay, s, sP[(ch_l * 8 + t) * USTRIDE + n]);
            g_carryT[((size_t)bb * NN + n) * NCH + ch0 + ch_l] = s;
        }
    }
}

// ---------------- kernel 2: scan_carry (warp-parallel, Kogge-Stone) ----------
__global__ void __launch_bounds__(256) scan_carry(
    const float* __restrict__ sd, float* __restrict__ carryT)
{
    const int wid = threadIdx.x >> 5, lane = threadIdx.x & 31;
    const int row = blockIdx.x * 8 + wid;          // 0..255 = b*NN + n
    const int n = row & (NN - 1);
    const float dp = sd[2 * NN + n];

    float4* p = (float4*)(carryT + (size_t)row * NCH) + lane * 4;
    float4 e0 = p[0], e1 = p[1], e2 = p[2], e3 = p[3];

    float l[16];
    l[0]  = e0.x;
    l[1]  = fmaf(dp, l[0],  e0.y);
    l[2]  = fmaf(dp, l[1],  e0.z);
    l[3]  = fmaf(dp, l[2],  e0.w);
    l[4]  = fmaf(dp, l[3],  e1.x);
    l[5]  = fmaf(dp, l[4],  e1.y);
    l[6]  = fmaf(dp, l[5],  e1.z);
    l[7]  = fmaf(dp, l[6],  e1.w);
    l[8]  = fmaf(dp, l[7],  e2.x);
    l[9]  = fmaf(dp, l[8],  e2.y);
    l[10] = fmaf(dp, l[9],  e2.z);
    l[11] = fmaf(dp, l[10], e2.w);
    l[12] = fmaf(dp, l[11], e3.x);
    l[13] = fmaf(dp, l[12], e3.y);
    l[14] = fmaf(dp, l[13], e3.z);
    l[15] = fmaf(dp, l[14], e3.w);

    const float dp2 = dp * dp, dp4 = dp2 * dp2, dp8 = dp4 * dp4, dp16 = dp8 * dp8;
    float s = l[15], f = dp16;
#pragma unroll
    for (int k = 1; k < 32; k <<= 1) {
        float t = __shfl_up_sync(0xffffffffu, s, k);
        if (lane >= k) s = fmaf(f, t, s);
        f = f * f;
    }
    float prev = __shfl_up_sync(0xffffffffu, s, 1);
    if (lane == 0) prev = 0.f;

    float c[16];
    c[0] = prev;
    float dpj = dp;
#pragma unroll
    for (int j = 1; j < 16; ++j) {
        c[j] = fmaf(dpj, prev, l[j - 1]);
        dpj *= dp;
    }
    p[0] = make_float4(c[0],  c[1],  c[2],  c[3]);
    p[1] = make_float4(c[4],  c[5],  c[6],  c[7]);
    p[2] = make_float4(c[8],  c[9],  c[10], c[11]);
    p[3] = make_float4(c[12], c[13], c[14], c[15]);
}

// ---------------- kernel 3: scan_final -> y bf16 hi/lo ----------------
__global__ void __launch_bounds__(256) scan_final(
    const float* __restrict__ P, const float* __restrict__ Ct,
    const float* __restrict__ sd, const float* __restrict__ carryT)
{
    const int n = threadIdx.x & 63;
    const int ch = blockIdx.x * 4 + (threadIdx.x >> 6);
    const int b = blockIdx.y;
    const float decay = sd[NN + n];
    size_t base = ((size_t)b * LL + (size_t)ch * TCH) * NN + n;
    float s = carryT[((size_t)b * NN + n) * NCH + ch];
#pragma unroll
    for (int t = 0; t < TCH; ++t) {
        size_t idx = base + (size_t)t * NN;
        s = fmaf(decay, s, P[idx]);
        float yv = Ct[idx] * s;
        split1(yv, g_yH[idx], g_yL[idx]);
    }
}

// ---------------- kernel 4: out = y @ Wo + bo (M-tile 128, N-tile 128, K=64) -----
#define OAH 0
#define OAL 16384
#define OBH 32768
#define OBL 49152
#define TCOUT_SMEM 65536

__global__ void __launch_bounds__(256, 2) tc_out(
    const float* __restrict__ bo, float* __restrict__ out)
{
    extern __shared__ char dsm[];
    const int tid = threadIdx.x;
    const int lane = tid & 31, w = tid >> 5;
    const int mw = (w >> 1) * 32;        // 4 m-warps
    const int nw = (w & 1) * 64;         // 2 n-warps
    const int m0 = blockIdx.x * 128;
    const int n0 = blockIdx.y * 128;

    const u32 sbase = s2u(dsm);
    const int arow = lane & 15, acol = (lane >> 4) * 8;
    const int brow = lane & 15;

#pragma unroll
    for (int i = tid; i < 128 * 8; i += 256) {
        int r = i >> 3, ch = i & 7;
        size_t gb = (size_t)(m0 + r) * 128 + ch * 16;
        u32 sw = SW128(r * 128 + ch * 16);
        CPA16(sbase + OAH + sw, (const char*)g_yH + gb);
        CPA16(sbase + OAL + sw, (const char*)g_yL + gb);
    }
#pragma unroll
    for (int i = tid; i < 64 * 16; i += 256) {
        int r = i >> 4, ch = i & 15;
        size_t gb = (size_t)r * 2048 + (size_t)n0 * 2 + ch * 16;
        u32 sw = (u32)(ch >> 3) * 8192 + SW128(r * 128 + (ch & 7) * 16);
        CPA16(sbase + OBH + sw, (const char*)g_WoH + gb);
        CPA16(sbase + OBL + sw, (const char*)g_WoL + gb);
    }
    CPA_COMMIT();
    CPA_WAIT0();
    __syncthreads();

    float acc[2][8][4];
#pragma unroll
    for (int mt = 0; mt < 2; ++mt)
#pragma unroll
        for (int nt = 0; nt < 8; ++nt)
#pragma unroll
            for (int q = 0; q < 4; ++q) acc[mt][nt][q] = 0.f;

#pragma unroll
    for (int ks = 0; ks < 4; ++ks) {
        u32 ah[2][4], al[2][4];
#pragma unroll
        for (int mt = 0; mt < 2; ++mt) {
            u32 off = SW128((mw + mt * 16 + arow) * 128 + (ks * 16 + acol) * 2);
            LDSM4(ah[mt], sbase + OAH + off);
            LDSM4(al[mt], sbase + OAL + off);
        }
#pragma unroll
        for (int nt = 0; nt < 8; ++nt) {
            int col = nw + nt * 8;
            u32 off = (u32)(col >> 6) * 8192 +
                      SW128((ks * 16 + brow) * 128 + (col & 63) * 2);
            u32 bh[2], bl[2];
            LDSM2T(bh, sbase + OBH + off);
            LDSM2T(bl, sbase + OBL + off);
#pragma unroll
            for (int mt = 0; mt < 2; ++mt) {
                MMA(acc[mt][nt], ah[mt], bh);
                MMA(acc[mt][nt], ah[mt], bl);
                MMA(acc[mt][nt], al[mt], bh);
            }
        }
    }

#pragma unroll
    for (int mt = 0; mt < 2; ++mt)
#pragma unroll
        for (int nt = 0; nt < 8; ++nt) {
            int r0 = m0 + mw + mt * 16 + (lane >> 2);
            int col = n0 + nw + nt * 8 + 2 * (lane & 3);
            float b0v = bo[col], b1v = bo[col + 1];
            *(float2*)&out[(size_t)r0 * DD + col] =
                make_float2(acc[mt][nt][0] + b0v, acc[mt][nt][1] + b1v);
            *(float2*)&out[(size_t)(r0 + 8) * DD + col] =
                make_float2(acc[mt][nt][2] + b0v, acc[mt][nt][3] + b1v);
        }
}

// ---------------- launch ----------------
extern "C" void kernel_launch(void* const* d_in, const int* in_sizes, int n_in,
                              void* d_out, int out_size)
{
    const float* x      = (const float*)d_in[0];
    const float* conv_w = (const float*)d_in[1];
    const float* conv_b = (const float*)d_in[2];
    const float* Wp     = (const float*)d_in[3];
    const float* bp     = (const float*)d_in[4];
    const float* Ws     = (const float*)d_in[5];
    const float* bs     = (const float*)d_in[6];
    const float* A_log  = (const float*)d_in[7];
    const float* dt_log = (const float*)d_in[8];
    const float* Wo     = (const float*)d_in[9];
    const float* bo     = (const float*)d_in[10];
    float* out = (float*)d_out;

    float *p_p, *ct_p, *carry_p, *ebias_p, *sd_p;
    cudaGetSymbolAddress((void**)&p_p,     g_P);
    cudaGetSymbolAddress((void**)&ct_p,    g_Ct);
    cudaGetSymbolAddress((void**)&carry_p, g_carryT);
    cudaGetSymbolAddress((void**)&ebias_p, g_ebias);
    cudaGetSymbolAddress((void**)&sd_p,    g_sd);

    static int attr_done = 0;
    if (!attr_done) {
        cudaFuncSetAttribute(tc_fused, cudaFuncAttributeMaxDynamicSharedMemorySize, FUSED_SMEM);
        cudaFuncSetAttribute(tc_out, cudaFuncAttributeMaxDynamicSharedMemorySize, TCOUT_SMEM);
        attr_done = 1;
    }

    // 0) weights -> bf16 hi/lo, effective biases, scan constants
    prep_kernel<<<64, 256>>>(Wp, Ws, Wo, conv_b, bp, bs, A_log, dt_log, ebias_p, sd_p);

    // 1) fused conv + gate GEMM + u GEMM -> P, Ct, chunk partials (2 blocks/SM)
    tc_fused<<<MM / 64, 384, FUSED_SMEM>>>(x, conv_w, ebias_p, sd_p);

    // 2) carry combine (exclusive carries in place)
    scan_carry<<<32, 256>>>(sd_p, carry_p);

    // 3) scan_final -> y (bf16 hi/lo)
    scan_final<<<dim3(NCH / 4, BB), 256>>>(p_p, ct_p, sd_p, carry_p);

    // 4) out = y @ Wo + bo (M-tile 128, N-tile 128; 1024 blocks, 2/SM)
    tc_out<<<dim3(MM / 128, DD / 128), 256, TCOUT_SMEM>>>(bo, out);
}

// round 17
// speedup vs baseline: 1.4230x; 1.2579x over previous
#include <cuda_runtime.h>
#include <cuda_bf16.h>
#include <math.h>
#include <stdint.h>

// Problem dims (fixed by the dataset)
#define BB 4
#define LL 4096
#define DD 1024
#define NN 64
#define MM (BB * LL)
#define NCH 512
#define TCH (LL / NCH)    // 8

typedef unsigned int u32;
typedef __nv_bfloat16 bf16;

// ---------------- scratch (device globals: no allocation allowed) ----------------
__device__ bf16 g_WpH[DD * 2 * NN], g_WpL[DD * 2 * NN];   // [1024][128]
__device__ bf16 g_WsH[DD * NN],     g_WsL[DD * NN];       // [1024][64]
__device__ bf16 g_WoH[NN * DD],     g_WoL[NN * DD];       // [64][1024]
__device__ float g_P [MM * NN];                            // dt * Bt * u
__device__ float g_Ct[MM * NN];
__device__ bf16  g_yH[MM * NN], g_yL[MM * NN];            // [16384][64]
__device__ float g_carryT[BB * NN * NCH];                 // transposed partials
__device__ float g_ebias[3 * NN];
__device__ float g_sd[3 * NN];                            // dt | decay | decay^TCH

// ---------------- helpers ----------------
#define SW128(o) ((u32)(o) ^ ((((u32)(o)) >> 3) & 0x70))

__device__ __forceinline__ u32 s2u(const void* p) {
    u32 a;
    asm("{ .reg .u64 t; cvta.to.shared.u64 t, %1; cvt.u32.u64 %0, t; }" : "=r"(a) : "l"(p));
    return a;
}
__device__ __forceinline__ float sp(float v) { return v > 20.f ? v : log1pf(expf(v)); }

#define LDSM4(r, a)                                                                    \
    asm volatile("ldmatrix.sync.aligned.m8n8.x4.shared.b16 {%0,%1,%2,%3}, [%4];"      \
                 : "=r"((r)[0]), "=r"((r)[1]), "=r"((r)[2]), "=r"((r)[3]) : "r"(a))
#define LDSM2T(r, a)                                                                   \
    asm volatile("ldmatrix.sync.aligned.m8n8.x2.trans.shared.b16 {%0,%1}, [%2];"      \
                 : "=r"((r)[0]), "=r"((r)[1]) : "r"(a))
#define MMA(d, a, b)                                                                   \
    asm volatile("mma.sync.aligned.m16n8k16.row.col.f32.bf16.bf16.f32 "               \
                 "{%0,%1,%2,%3}, {%4,%5,%6,%7}, {%8,%9}, {%0,%1,%2,%3};"              \
                 : "+f"((d)[0]), "+f"((d)[1]), "+f"((d)[2]), "+f"((d)[3])             \
                 : "r"((a)[0]), "r"((a)[1]), "r"((a)[2]), "r"((a)[3]),                \
                   "r"((b)[0]), "r"((b)[1]))

#define CPA16(sa, gp)                                                                  \
    asm volatile("cp.async.cg.shared.global [%0], [%1], 16;" :: "r"((u32)(sa)), "l"(gp))
#define CPA_COMMIT() asm volatile("cp.async.commit_group;" ::: "memory")
#define CPA_WAIT0()  asm volatile("cp.async.wait_group 0;" ::: "memory")

__device__ __forceinline__ void split1(float v, bf16& h, bf16& l) {
    h = __float2bfloat16(v);
    l = __float2bfloat16(v - __bfloat162float(h));
}
__device__ __forceinline__ void split_store8(char* hiP, char* loP, float4 v) {
    bf16 h0, l0, h1, l1, h2, l2, h3, l3;
    split1(v.x, h0, l0); split1(v.y, h1, l1);
    split1(v.z, h2, l2); split1(v.w, h3, l3);
    __nv_bfloat162 hp0 = {h0, h1}, hp1 = {h2, h3};
    __nv_bfloat162 lp0 = {l0, l1}, lp1 = {l2, l3};
    *(uint2*)hiP = make_uint2(*(u32*)&hp0, *(u32*)&hp1);
    *(uint2*)loP = make_uint2(*(u32*)&lp0, *(u32*)&lp1);
}
__device__ __forceinline__ float4 f4fma(float4 acc, float4 a, float4 b) {
    acc.x = fmaf(a.x, b.x, acc.x); acc.y = fmaf(a.y, b.y, acc.y);
    acc.z = fmaf(a.z, b.z, acc.z); acc.w = fmaf(a.w, b.w, acc.w);
    return acc;
}

// ---------------- kernel 0a: ebias[n] = bp[n] + conv_b @ Wp[:, n]  (n < 128) -----
// Block-per-n, 256-thread deterministic tree reduce. Replaces the serial
// 1024-FMA tail that ran on 128 threads of one block.
__global__ void __launch_bounds__(256) ebias_kernel(
    const float* __restrict__ Wp, const float* __restrict__ cb,
    const float* __restrict__ bp, float* __restrict__ ebias)
{
    __shared__ float red[256];
    const int n = blockIdx.x;       // 0..127
    const int tid = threadIdx.x;
    float s = 0.f;
#pragma unroll
    for (int i = 0; i < DD / 256; ++i) {
        int d = i * 256 + tid;
        s = fmaf(cb[d], Wp[(size_t)d * 2 * NN + n], s);
    }
    red[tid] = s;
    __syncthreads();
#pragma unroll
    for (int k = 128; k > 0; k >>= 1) {
        if (tid < k) red[tid] += red[tid + k];
        __syncthreads();
    }
    if (tid == 0) ebias[n] = bp[n] + red[0];
}

// ---------------- kernel 0b: weight bf16 hi/lo split + bs + scan consts ----------
__global__ void __launch_bounds__(256) prep_kernel(
    const float* __restrict__ Wp, const float* __restrict__ Ws,
    const float* __restrict__ Wo, const float* __restrict__ bs,
    const float* __restrict__ A_log, const float* __restrict__ dt_log,
    float* __restrict__ ebias, float* __restrict__ sd)
{
    const int gtid = blockIdx.x * 256 + threadIdx.x;
    const int NT = gridDim.x * 256;

    for (int i = gtid; i < DD * 2 * NN; i += NT) split1(Wp[i], g_WpH[i], g_WpL[i]);
    for (int i = gtid; i < DD * NN;     i += NT) split1(Ws[i], g_WsH[i], g_WsL[i]);
    for (int i = gtid; i < NN * DD;     i += NT) split1(Wo[i], g_WoH[i], g_WoL[i]);

    if (gtid < NN) {
        ebias[2 * NN + gtid] = bs[gtid];
        int n = gtid;
        float dt = sp(dt_log[n]);
        float decay = 1.f - dt * sp(A_log[n]);
        float dp = decay;
#pragma unroll
        for (int i = 0; i < 3; ++i) dp *= dp;      // decay^8 (TCH = 2^3)
        sd[n] = dt;
        sd[NN + n] = decay;
        sd[2 * NN + n] = dp;
    }
}

// ---------------- kernel 1: fused conv + gates + u -> P, Ct, chunk partials ------
// SINGLE-buffered smem (99 KB) -> 2 blocks/SM, grid 256 = one wave.
#define SFX   0          // raw x: 67 rows x 256B          (17408)
#define SBPH  17408      // Wp hi: 64x128, 2 panels SW128  (16384)
#define SBPL  33792
#define SBSH  50176      // Ws hi: 64x64 SW128             (8192)
#define SBSL  58368
#define SACH  66560      // conv split hi                  (8192)
#define SACL  74752
#define SAXH  82944      // x split hi
#define SAXL  91136
#define FUSED_SMEM 99328
#define USTRIDE 66       // u / P exchange row stride (floats)

__global__ void __launch_bounds__(384, 2) tc_fused(
    const float* __restrict__ x, const float* __restrict__ cw,
    const float* __restrict__ ebias, const float* __restrict__ sd)
{
    extern __shared__ char dsm[];
    const int tid = threadIdx.x;
    const int lane = tid & 31, w = tid >> 5;
    const int m0 = blockIdx.x * 64;
    const bool seqstart = ((m0 & (LL - 1)) == 0);

    const bool is_gate = (w < 8);
    const int mw = is_gate ? ((w >> 2) * 32) : (((w - 8) >> 1) * 32);
    const int nw = is_gate ? ((w & 3) * 32) : (((w - 8) & 1) * 32);

    float acc[2][4][4];
#pragma unroll
    for (int mt = 0; mt < 2; ++mt)
#pragma unroll
        for (int nt = 0; nt < 4; ++nt)
#pragma unroll
            for (int q = 0; q < 4; ++q) acc[mt][nt][q] = 0.f;

    const int arow = lane & 15, acol = (lane >> 4) * 8;
    const int brow = lane & 15;

    const u32 sbase = s2u(dsm);

    auto stageX = [&](int kt) {
        for (int i = tid; i < 67 * 16; i += 384) {
            int rr = i >> 4, ch = i & 15;
            if (seqstart && rr < 3) {
                *(uint4*)(dsm + SFX + rr * 256 + ch * 16) = make_uint4(0, 0, 0, 0);
            } else {
                CPA16(sbase + SFX + rr * 256 + ch * 16,
                      x + (size_t)(m0 - 3 + rr) * DD + kt * 64 + ch * 4);
            }
        }
    };
    auto stageB = [&](int kt) {
        for (int i = tid; i < 64 * 16; i += 384) {
            int r = i >> 4, ch = i & 15;
            size_t gb = (size_t)(kt * 64 + r) * 256 + ch * 16;
            u32 sw = (u32)(ch >> 3) * 8192 + SW128(r * 128 + (ch & 7) * 16);
            CPA16(sbase + SBPH + sw, (const char*)g_WpH + gb);
            CPA16(sbase + SBPL + sw, (const char*)g_WpL + gb);
        }
        for (int i = tid; i < 64 * 8; i += 384) {
            int r = i >> 3, ch = i & 7;
            size_t gb = (size_t)(kt * 64 + r) * 128 + ch * 16;
            u32 sw = SW128(r * 128 + ch * 16);
            CPA16(sbase + SBSH + sw, (const char*)g_WsH + gb);
            CPA16(sbase + SBSL + sw, (const char*)g_WsL + gb);
        }
    };

    stageX(0);
    stageB(0);
    CPA_COMMIT();

    for (int kt = 0; kt < DD / 64; ++kt) {
        CPA_WAIT0();
        __syncthreads();   // X(kt), B(kt) visible

        // ---- conv + split -> SACH/SACL; raw x split -> SAXH/SAXL ----
#pragma unroll
        for (int i = tid; i < 64 * 16; i += 384) {
            int r = i >> 4, ch = i & 15;
            float4 xm3 = *(const float4*)(dsm + SFX + (r + 0) * 256 + ch * 16);
            float4 xm2 = *(const float4*)(dsm + SFX + (r + 1) * 256 + ch * 16);
            float4 xm1 = *(const float4*)(dsm + SFX + (r + 2) * 256 + ch * 16);
            float4 xc  = *(const float4*)(dsm + SFX + (r + 3) * 256 + ch * 16);
            int dcol = kt * 64 + ch * 4;
            float4 w0 = *(const float4*)(cw + 0 * DD + dcol);
            float4 w1 = *(const float4*)(cw + 1 * DD + dcol);
            float4 w2 = *(const float4*)(cw + 2 * DD + dcol);
            float4 w3 = *(const float4*)(cw + 3 * DD + dcol);
            float4 o = make_float4(0.f, 0.f, 0.f, 0.f);
            o = f4fma(o, w0, xm3); o = f4fma(o, w1, xm2);
            o = f4fma(o, w2, xm1); o = f4fma(o, w3, xc);
            u32 sw = SW128(r * 128 + ch * 8);
            split_store8(dsm + SACH + sw, dsm + SACL + sw, o);
            split_store8(dsm + SAXH + sw, dsm + SAXL + sw, xc);
        }
        __syncthreads();   // splits ready; X no longer needed

        // stage next X now -> overlaps MMA below
        if (kt + 1 < DD / 64) stageX(kt + 1);

        // ---- MMA (reads splits + B) ----
        const u32 aH = sbase + (is_gate ? SACH : SAXH);
        const u32 aL = sbase + (is_gate ? SACL : SAXL);
        const u32 bH = sbase + (is_gate ? SBPH : SBSH);
        const u32 bL = sbase + (is_gate ? SBPL : SBSL);
#pragma unroll
        for (int ks = 0; ks < 4; ++ks) {
            u32 ah[2][4], al[2][4];
#pragma unroll
            for (int mt = 0; mt < 2; ++mt) {
                u32 off = SW128((mw + mt * 16 + arow) * 128 + (ks * 16 + acol) * 2);
                LDSM4(ah[mt], aH + off);
                LDSM4(al[mt], aL + off);
            }
#pragma unroll
            for (int nt = 0; nt < 4; ++nt) {
                int col = nw + nt * 8;
                u32 off = (u32)(col >> 6) * 8192 +
                          SW128((ks * 16 + brow) * 128 + (col & 63) * 2);
                u32 bh[2], bl[2];
                LDSM2T(bh, bH + off);
                LDSM2T(bl, bL + off);
#pragma unroll
                for (int mt = 0; mt < 2; ++mt) {
                    MMA(acc[mt][nt], ah[mt], bh);
                    MMA(acc[mt][nt], ah[mt], bl);
                    MMA(acc[mt][nt], al[mt], bh);
                }
            }
        }
        __syncthreads();   // all B reads done

        if (kt + 1 < DD / 64) {
            stageB(kt + 1);
            CPA_COMMIT();  // covers this iteration's X + B stages
        }
    }

    // ---- epilogue: u warps -> smem exchange; gate warps -> P (gmem + smem), Ct --
    float* sU = (float*)dsm;                 // SFX region
    float* sP = (float*)(dsm + SBPH);        // SBPH+SBPL region
    if (!is_gate) {
#pragma unroll
        for (int mt = 0; mt < 2; ++mt)
#pragma unroll
            for (int nt = 0; nt < 4; ++nt) {
                int r = mw + mt * 16 + (lane >> 2);
                int col = nw + nt * 8 + 2 * (lane & 3);
                float b0v = ebias[2 * NN + col], b1v = ebias[2 * NN + col + 1];
                sU[r * USTRIDE + col]           = acc[mt][nt][0] + b0v;
                sU[r * USTRIDE + col + 1]       = acc[mt][nt][1] + b1v;
                sU[(r + 8) * USTRIDE + col]     = acc[mt][nt][2] + b0v;
                sU[(r + 8) * USTRIDE + col + 1] = acc[mt][nt][3] + b1v;
            }
    }
    __syncthreads();
    if (is_gate) {
#pragma unroll
        for (int mt = 0; mt < 2; ++mt)
#pragma unroll
            for (int nt = 0; nt < 4; ++nt) {
                int r = mw + mt * 16 + (lane >> 2);
                int col = nw + nt * 8 + 2 * (lane & 3);
                float b0v = ebias[col], b1v = ebias[col + 1];
                float vx = acc[mt][nt][0] + b0v, vy = acc[mt][nt][1] + b1v;
                float vz = acc[mt][nt][2] + b0v, vw = acc[mt][nt][3] + b1v;
                if (col < 64) {
                    float dt0 = sd[col], dt1 = sd[col + 1];
                    float p0 = dt0 * sp(vx) * sU[r * USTRIDE + col];
                    float p1 = dt1 * sp(vy) * sU[r * USTRIDE + col + 1];
                    float p2 = dt0 * sp(vz) * sU[(r + 8) * USTRIDE + col];
                    float p3 = dt1 * sp(vw) * sU[(r + 8) * USTRIDE + col + 1];
                    *(float2*)&g_P[(size_t)(m0 + r) * NN + col] = make_float2(p0, p1);
                    *(float2*)&g_P[(size_t)(m0 + r + 8) * NN + col] = make_float2(p2, p3);
                    sP[r * USTRIDE + col]           = p0;
                    sP[r * USTRIDE + col + 1]       = p1;
                    sP[(r + 8) * USTRIDE + col]     = p2;
                    sP[(r + 8) * USTRIDE + col + 1] = p3;
                } else {
                    vx = tanhf(vx); vy = tanhf(vy); vz = tanhf(vz); vw = tanhf(vw);
                    *(float2*)&g_Ct[(size_t)(m0 + r) * NN + col - 64] = make_float2(vx, vy);
                    *(float2*)&g_Ct[(size_t)(m0 + r + 8) * NN + col - 64] = make_float2(vz, vw);
                }
            }
    }
    __syncthreads();

    // ---- fused scan_partial: 8 chunks x 64 n over this block's 64 rows ----
    {
        const int bb = m0 >> 12;                       // m0 / LL
        const int ch0 = (m0 & (LL - 1)) >> 3;          // first chunk index
        for (int pair = tid; pair < 8 * 64; pair += 384) {
            int ch_l = pair >> 6, n = pair & 63;
            float decay = sd[NN + n];
            float s = 0.f;
#pragma unroll
            for (int t = 0; t < 8; ++t)
                s = fmaf(decay, s, sP[(ch_l * 8 + t) * USTRIDE + n]);
            g_carryT[((size_t)bb * NN + n) * NCH + ch0 + ch_l] = s;
        }
    }
}

// ---------------- kernel 2: scan_carry (warp-parallel, Kogge-Stone) ----------
__global__ void __launch_bounds__(256) scan_carry(
    const float* __restrict__ sd, float* __restrict__ carryT)
{
    const int wid = threadIdx.x >> 5, lane = threadIdx.x & 31;
    const int row = blockIdx.x * 8 + wid;          // 0..255 = b*NN + n
    const int n = row & (NN - 1);
    const float dp = sd[2 * NN + n];

    float4* p = (float4*)(carryT + (size_t)row * NCH) + lane * 4;
    float4 e0 = p[0], e1 = p[1], e2 = p[2], e3 = p[3];

    float l[16];
    l[0]  = e0.x;
    l[1]  = fmaf(dp, l[0],  e0.y);
    l[2]  = fmaf(dp, l[1],  e0.z);
    l[3]  = fmaf(dp, l[2],  e0.w);
    l[4]  = fmaf(dp, l[3],  e1.x);
    l[5]  = fmaf(dp, l[4],  e1.y);
    l[6]  = fmaf(dp, l[5],  e1.z);
    l[7]  = fmaf(dp, l[6],  e1.w);
    l[8]  = fmaf(dp, l[7],  e2.x);
    l[9]  = fmaf(dp, l[8],  e2.y);
    l[10] = fmaf(dp, l[9],  e2.z);
    l[11] = fmaf(dp, l[10], e2.w);
    l[12] = fmaf(dp, l[11], e3.x);
    l[13] = fmaf(dp, l[12], e3.y);
    l[14] = fmaf(dp, l[13], e3.z);
    l[15] = fmaf(dp, l[14], e3.w);

    const float dp2 = dp * dp, dp4 = dp2 * dp2, dp8 = dp4 * dp4, dp16 = dp8 * dp8;
    float s = l[15], f = dp16;
#pragma unroll
    for (int k = 1; k < 32; k <<= 1) {
        float t = __shfl_up_sync(0xffffffffu, s, k);
        if (lane >= k) s = fmaf(f, t, s);
        f = f * f;
    }
    float prev = __shfl_up_sync(0xffffffffu, s, 1);
    if (lane == 0) prev = 0.f;

    float c[16];
    c[0] = prev;
    float dpj = dp;
#pragma unroll
    for (int j = 1; j < 16; ++j) {
        c[j] = fmaf(dpj, prev, l[j - 1]);
        dpj *= dp;
    }
    p[0] = make_float4(c[0],  c[1],  c[2],  c[3]);
    p[1] = make_float4(c[4],  c[5],  c[6],  c[7]);
    p[2] = make_float4(c[8],  c[9],  c[10], c[11]);
    p[3] = make_float4(c[12], c[13], c[14], c[15]);
}

// ---------------- kernel 3: scan_final -> y bf16 hi/lo ----------------
__global__ void __launch_bounds__(256) scan_final(
    const float* __restrict__ P, const float* __restrict__ Ct,
    const float* __restrict__ sd, const float* __restrict__ carryT)
{
    const int n = threadIdx.x & 63;
    const int ch = blockIdx.x * 4 + (threadIdx.x >> 6);
    const int b = blockIdx.y;
    const float decay = sd[NN + n];
    size_t base = ((size_t)b * LL + (size_t)ch * TCH) * NN + n;
    float s = carryT[((size_t)b * NN + n) * NCH + ch];
#pragma unroll
    for (int t = 0; t < TCH; ++t) {
        size_t idx = base + (size_t)t * NN;
        s = fmaf(decay, s, P[idx]);
        float yv = Ct[idx] * s;
        split1(yv, g_yH[idx], g_yL[idx]);
    }
}

// ---------------- kernel 4: out = y @ Wo + bo (M-tile 128, N-tile 128, K=64) -----
#define OAH 0
#define OAL 16384
#define OBH 32768
#define OBL 49152
#define TCOUT_SMEM 65536

__global__ void __launch_bounds__(256, 2) tc_out(
    const float* __restrict__ bo, float* __restrict__ out)
{
    extern __shared__ char dsm[];
    const int tid = threadIdx.x;
    const int lane = tid & 31, w = tid >> 5;
    const int mw = (w >> 1) * 32;        // 4 m-warps
    const int nw = (w & 1) * 64;         // 2 n-warps
    const int m0 = blockIdx.x * 128;
    const int n0 = blockIdx.y * 128;

    const u32 sbase = s2u(dsm);
    const int arow = lane & 15, acol = (lane >> 4) * 8;
    const int brow = lane & 15;

#pragma unroll
    for (int i = tid; i < 128 * 8; i += 256) {
        int r = i >> 3, ch = i & 7;
        size_t gb = (size_t)(m0 + r) * 128 + ch * 16;
        u32 sw = SW128(r * 128 + ch * 16);
        CPA16(sbase + OAH + sw, (const char*)g_yH + gb);
        CPA16(sbase + OAL + sw, (const char*)g_yL + gb);
    }
#pragma unroll
    for (int i = tid; i < 64 * 16; i += 256) {
        int r = i >> 4, ch = i & 15;
        size_t gb = (size_t)r * 2048 + (size_t)n0 * 2 + ch * 16;
        u32 sw = (u32)(ch >> 3) * 8192 + SW128(r * 128 + (ch & 7) * 16);
        CPA16(sbase + OBH + sw, (const char*)g_WoH + gb);
        CPA16(sbase + OBL + sw, (const char*)g_WoL + gb);
    }
    CPA_COMMIT();
    CPA_WAIT0();
    __syncthreads();

    float acc[2][8][4];
#pragma unroll
    for (int mt = 0; mt < 2; ++mt)
#pragma unroll
        for (int nt = 0; nt < 8; ++nt)
#pragma unroll
            for (int q = 0; q < 4; ++q) acc[mt][nt][q] = 0.f;

#pragma unroll
    for (int ks = 0; ks < 4; ++ks) {
        u32 ah[2][4], al[2][4];
#pragma unroll
        for (int mt = 0; mt < 2; ++mt) {
            u32 off = SW128((mw + mt * 16 + arow) * 128 + (ks * 16 + acol) * 2);
            LDSM4(ah[mt], sbase + OAH + off);
            LDSM4(al[mt], sbase + OAL + off);
        }
#pragma unroll
        for (int nt = 0; nt < 8; ++nt) {
            int col = nw + nt * 8;
            u32 off = (u32)(col >> 6) * 8192 +
                      SW128((ks * 16 + brow) * 128 + (col & 63) * 2);
            u32 bh[2], bl[2];
            LDSM2T(bh, sbase + OBH + off);
            LDSM2T(bl, sbase + OBL + off);
#pragma unroll
            for (int mt = 0; mt < 2; ++mt) {
                MMA(acc[mt][nt], ah[mt], bh);
                MMA(acc[mt][nt], ah[mt], bl);
                MMA(acc[mt][nt], al[mt], bh);
            }
        }
    }

#pragma unroll
    for (int mt = 0; mt < 2; ++mt)
#pragma unroll
        for (int nt = 0; nt < 8; ++nt) {
            int r0 = m0 + mw + mt * 16 + (lane >> 2);
            int col = n0 + nw + nt * 8 + 2 * (lane & 3);
            float b0v = bo[col], b1v = bo[col + 1];
            *(float2*)&out[(size_t)r0 * DD + col] =
                make_float2(acc[mt][nt][0] + b0v, acc[mt][nt][1] + b1v);
            *(float2*)&out[(size_t)(r0 + 8) * DD + col] =
                make_float2(acc[mt][nt][2] + b0v, acc[mt][nt][3] + b1v);
        }
}

// ---------------- launch ----------------
extern "C" void kernel_launch(void* const* d_in, const int* in_sizes, int n_in,
                              void* d_out, int out_size)
{
    const float* x      = (const float*)d_in[0];
    const float* conv_w = (const float*)d_in[1];
    const float* conv_b = (const float*)d_in[2];
    const float* Wp     = (const float*)d_in[3];
    const float* bp     = (const float*)d_in[4];
    const float* Ws     = (const float*)d_in[5];
    const float* bs     = (const float*)d_in[6];
    const float* A_log  = (const float*)d_in[7];
    const float* dt_log = (const float*)d_in[8];
    const float* Wo     = (const float*)d_in[9];
    const float* bo     = (const float*)d_in[10];
    float* out = (float*)d_out;

    float *p_p, *ct_p, *carry_p, *ebias_p, *sd_p;
    cudaGetSymbolAddress((void**)&p_p,     g_P);
    cudaGetSymbolAddress((void**)&ct_p,    g_Ct);
    cudaGetSymbolAddress((void**)&carry_p, g_carryT);
    cudaGetSymbolAddress((void**)&ebias_p, g_ebias);
    cudaGetSymbolAddress((void**)&sd_p,    g_sd);

    static int attr_done = 0;
    if (!attr_done) {
        cudaFuncSetAttribute(tc_fused, cudaFuncAttributeMaxDynamicSharedMemorySize, FUSED_SMEM);
        cudaFuncSetAttribute(tc_out, cudaFuncAttributeMaxDynamicSharedMemorySize, TCOUT_SMEM);
        attr_done = 1;
    }

    // 0) ebias reduction (parallel) + weight splits / bs / scan constants
    ebias_kernel<<<2 * NN, 256>>>(Wp, conv_b, bp, ebias_p);
    prep_kernel<<<64, 256>>>(Wp, Ws, Wo, bs, A_log, dt_log, ebias_p, sd_p);

    // 1) fused conv + gate GEMM + u GEMM -> P, Ct, chunk partials (2 blocks/SM)
    tc_fused<<<MM / 64, 384, FUSED_SMEM>>>(x, conv_w, ebias_p, sd_p);

    // 2) carry combine (exclusive carries in place)
    scan_carry<<<32, 256>>>(sd_p, carry_p);

    // 3) scan_final -> y (bf16 hi/lo)
    scan_final<<<dim3(NCH / 4, BB), 256>>>(p_p, ct_p, sd_p, carry_p);

    // 4) out = y @ Wo + bo (M-tile 128, N-tile 128; 1024 blocks, 2/SM)
    tc_out<<<dim3(MM / 128, DD / 128), 256, TCOUT_SMEM>>>(bo, out);
}